// round 1
// baseline (speedup 1.0000x reference)
#include <cuda_runtime.h>
#include <cuda_bf16.h>

#define N_NODES 50000
#define N_EDGES 850000
#define F_INF   256
#define FH      64
#define NHEADS  8
#define NCLASSF 40
#define ALPHAF  0.2f
#define D1      (NHEADS * FH)   // 512

// ---------------- device scratch (globals; no allocation allowed) ----------
__device__ float g_H1[(size_t)N_NODES * D1];   // layer-1 per-head features
__device__ float g_XC[(size_t)N_NODES * D1];   // concat(elu(head outputs))
__device__ float g_S1s[N_NODES * NHEADS];
__device__ float g_S1d[N_NODES * NHEADS];
__device__ float g_H2[(size_t)N_NODES * FH];
__device__ float g_XO[(size_t)N_NODES * FH];
__device__ float g_S2s[N_NODES];
__device__ float g_S2d[N_NODES];
__device__ int   g_rowptr[N_NODES + 1];
__device__ int   g_cnt[N_NODES];
__device__ int   g_pos[N_NODES];
__device__ int   g_dsts[N_EDGES];

__device__ __forceinline__ float leakyv(float v) { return v > 0.f ? v : ALPHAF * v; }
__device__ __forceinline__ float eluv(float v)   { return v > 0.f ? v : expm1f(v); }

// ---------------- CSR build -------------------------------------------------
__global__ void k_zero_cnt() {
    int i = blockIdx.x * blockDim.x + threadIdx.x;
    if (i < N_NODES) g_cnt[i] = 0;
}

__global__ void k_hist(const int* __restrict__ src) {
    int e = blockIdx.x * blockDim.x + threadIdx.x;
    if (e < N_EDGES) atomicAdd(&g_cnt[src[e]], 1);
}

// one-block exclusive scan over 50000 counts (chunk-per-thread + shared scan)
__global__ __launch_bounds__(1024) void k_scan() {
    __shared__ int s[1024];
    const int CH = 49;  // 1024*49 >= 50000
    int t = threadIdx.x;
    int start = t * CH;
    int end = start + CH; if (end > N_NODES) end = N_NODES;
    int sum = 0;
    for (int i = start; i < end; i++) sum += g_cnt[i];
    s[t] = sum;
    __syncthreads();
    for (int off = 1; off < 1024; off <<= 1) {
        int v = (t >= off) ? s[t - off] : 0;
        __syncthreads();
        s[t] += v;
        __syncthreads();
    }
    int run = (t == 0) ? 0 : s[t - 1];
    for (int i = start; i < end; i++) {
        g_rowptr[i] = run;
        g_pos[i] = run;
        run += g_cnt[i];
    }
    if (t == 0) g_rowptr[N_NODES] = s[1023];
}

__global__ void k_scatter(const int* __restrict__ src, const int* __restrict__ dst) {
    int e = blockIdx.x * blockDim.x + threadIdx.x;
    if (e < N_EDGES) {
        int p = atomicAdd(&g_pos[src[e]], 1);
        g_dsts[p] = dst[e];
    }
}

// ---------------- fp32 tiled GEMM: C[M, gridDim.y*64] = A[M,K] @ B ---------
// B viewed as gridDim.y consecutive [K,64] matrices (covers W[8,256,64] and Wo[512,64]).
__global__ __launch_bounds__(256) void k_gemm(const float* __restrict__ A,
                                              const float* __restrict__ B,
                                              float* __restrict__ C,
                                              int M, int K, int ldc) {
    const int BM = 128, BN = 64, BK = 16;
    __shared__ float Xs[BK][BM + 4];   // transposed A tile
    __shared__ float Ws[BK][BN + 4];
    int t  = threadIdx.x;
    int tx = t & 15;          // N dir (x4)
    int ty = t >> 4;          // M dir (x8)
    int m0 = blockIdx.x * BM;
    int n0 = blockIdx.y * BN;
    const float* Bp = B + (size_t)blockIdx.y * K * BN;

    float acc[8][4];
#pragma unroll
    for (int i = 0; i < 8; i++)
#pragma unroll
        for (int j = 0; j < 4; j++) acc[i][j] = 0.f;

    for (int k0 = 0; k0 < K; k0 += BK) {
        // A tile: 128x16 floats, 2 float4 per thread, stored transposed
#pragma unroll
        for (int l = 0; l < 2; l++) {
            int idx = t + l * 256;
            int row = idx >> 2;
            int kq  = (idx & 3) * 4;
            float4 v = make_float4(0.f, 0.f, 0.f, 0.f);
            int m = m0 + row;
            if (m < M) v = *(const float4*)&A[(size_t)m * K + k0 + kq];
            Xs[kq + 0][row] = v.x;
            Xs[kq + 1][row] = v.y;
            Xs[kq + 2][row] = v.z;
            Xs[kq + 3][row] = v.w;
        }
        // B tile: 16x64, one float4 per thread
        {
            int row = t >> 4;
            int cq  = (t & 15) * 4;
            float4 v = *(const float4*)&Bp[(size_t)(k0 + row) * BN + cq];
            *(float4*)&Ws[row][cq] = v;
        }
        __syncthreads();
#pragma unroll
        for (int kk = 0; kk < BK; kk++) {
            float4 a0 = *(const float4*)&Xs[kk][ty * 8];
            float4 a1 = *(const float4*)&Xs[kk][ty * 8 + 4];
            float4 bv = *(const float4*)&Ws[kk][tx * 4];
            float a[8] = {a0.x, a0.y, a0.z, a0.w, a1.x, a1.y, a1.z, a1.w};
            float b[4] = {bv.x, bv.y, bv.z, bv.w};
#pragma unroll
            for (int i = 0; i < 8; i++)
#pragma unroll
                for (int j = 0; j < 4; j++) acc[i][j] = fmaf(a[i], b[j], acc[i][j]);
        }
        __syncthreads();
    }
#pragma unroll
    for (int i = 0; i < 8; i++) {
        int m = m0 + ty * 8 + i;
        if (m < M) {
            float4 v = make_float4(acc[i][0], acc[i][1], acc[i][2], acc[i][3]);
            *(float4*)&C[(size_t)m * ldc + n0 + tx * 4] = v;
        }
    }
}

// ---------------- attention scores, layer 1 --------------------------------
// block per node (256 thr = 8 warps), warp h handles head h: dot over 64 elems
__global__ __launch_bounds__(256) void k_scores1(const float* __restrict__ a) {
    int n = blockIdx.x;
    int w = threadIdx.x >> 5, lane = threadIdx.x & 31;
    const float* hrow = &g_H1[(size_t)n * D1 + w * FH];
    const float* av = a + w * 2 * FH;
    float v1 = hrow[lane] * av[lane]       + hrow[lane + 32] * av[lane + 32];
    float v2 = hrow[lane] * av[FH + lane]  + hrow[lane + 32] * av[FH + lane + 32];
#pragma unroll
    for (int off = 16; off; off >>= 1) {
        v1 += __shfl_xor_sync(0xffffffffu, v1, off);
        v2 += __shfl_xor_sync(0xffffffffu, v2, off);
    }
    if (lane == 0) {
        g_S1s[n * NHEADS + w] = v1;
        g_S1d[n * NHEADS + w] = v2;
    }
}

// ---------------- layer-1 aggregation (all 8 heads fused) ------------------
// block of 128 threads per node; thread owns 4 consecutive of 512 feat cols.
__global__ __launch_bounds__(128) void k_agg1() {
    int n = blockIdx.x, t = threadIdx.x;
    int head = t >> 4;  // (t*4)/64
    float ss = g_S1s[n * NHEADS + head];
    float4 acc = make_float4(0.f, 0.f, 0.f, 0.f);
    float rs = 0.f;
    int beg = g_rowptr[n], end = g_rowptr[n + 1];
    for (int e = beg; e < end; e++) {
        int d = g_dsts[e];
        float v = ss + g_S1d[d * NHEADS + head];
        float wgt = __expf(-leakyv(v));
        float4 hv = *(const float4*)&g_H1[(size_t)d * D1 + t * 4];
        acc.x = fmaf(wgt, hv.x, acc.x);
        acc.y = fmaf(wgt, hv.y, acc.y);
        acc.z = fmaf(wgt, hv.z, acc.z);
        acc.w = fmaf(wgt, hv.w, acc.w);
        rs += wgt;
    }
    float inv = 1.f / rs;
    float4 o = make_float4(eluv(acc.x * inv), eluv(acc.y * inv),
                           eluv(acc.z * inv), eluv(acc.w * inv));
    *(float4*)&g_XC[(size_t)n * D1 + t * 4] = o;
}

// ---------------- layer-2 scores (warp per node) ---------------------------
__global__ __launch_bounds__(256) void k_scores2(const float* __restrict__ ao) {
    int n = blockIdx.x * 8 + (threadIdx.x >> 5);
    if (n >= N_NODES) return;
    int lane = threadIdx.x & 31;
    const float* hrow = &g_H2[(size_t)n * FH];
    float v1 = hrow[lane] * ao[lane]      + hrow[lane + 32] * ao[lane + 32];
    float v2 = hrow[lane] * ao[FH + lane] + hrow[lane + 32] * ao[FH + lane + 32];
#pragma unroll
    for (int off = 16; off; off >>= 1) {
        v1 += __shfl_xor_sync(0xffffffffu, v1, off);
        v2 += __shfl_xor_sync(0xffffffffu, v2, off);
    }
    if (lane == 0) { g_S2s[n] = v1; g_S2d[n] = v2; }
}

// ---------------- layer-2 aggregation (64 threads per node) ----------------
__global__ __launch_bounds__(64) void k_agg2() {
    int n = blockIdx.x, t = threadIdx.x;
    float ss = g_S2s[n];
    float acc = 0.f, rs = 0.f;
    int beg = g_rowptr[n], end = g_rowptr[n + 1];
    for (int e = beg; e < end; e++) {
        int d = g_dsts[e];
        float v = ss + g_S2d[d];
        float wgt = __expf(-leakyv(v));
        acc = fmaf(wgt, g_H2[(size_t)d * FH + t], acc);
        rs += wgt;
    }
    g_XO[(size_t)n * FH + t] = eluv(acc / rs);
}

// ---------------- final classifier -----------------------------------------
__global__ __launch_bounds__(256) void k_final(const float* __restrict__ mw,
                                               const float* __restrict__ mb,
                                               float* __restrict__ out) {
    int idx = blockIdx.x * blockDim.x + threadIdx.x;
    if (idx >= N_NODES * NCLASSF) return;
    int n = idx / NCLASSF, c = idx - n * NCLASSF;
    const float* xo = &g_XO[(size_t)n * FH];
    const float* wv = &mw[c * FH];
    float s = mb[c];
#pragma unroll
    for (int k = 0; k < FH; k++) s = fmaf(xo[k], wv[k], s);
    out[idx] = s;
}

// ---------------- launch ----------------------------------------------------
extern "C" void kernel_launch(void* const* d_in, const int* in_sizes, int n_in,
                              void* d_out, int out_size) {
    const float* x    = (const float*)d_in[0];
    const int*   ei   = (const int*)d_in[1];
    const float* W    = (const float*)d_in[2];
    const float* a    = (const float*)d_in[3];
    const float* Wo   = (const float*)d_in[4];
    const float* ao   = (const float*)d_in[5];
    const float* mw   = (const float*)d_in[6];
    const float* mb   = (const float*)d_in[7];
    float* out = (float*)d_out;

    const int* src = ei;
    const int* dst = ei + N_EDGES;

    float *pH1, *pXC, *pH2;
    cudaGetSymbolAddress((void**)&pH1, g_H1);
    cudaGetSymbolAddress((void**)&pXC, g_XC);
    cudaGetSymbolAddress((void**)&pH2, g_H2);

    // CSR build
    k_zero_cnt<<<(N_NODES + 255) / 256, 256>>>();
    k_hist<<<(N_EDGES + 255) / 256, 256>>>(src);
    k_scan<<<1, 1024>>>();
    k_scatter<<<(N_EDGES + 255) / 256, 256>>>(src, dst);

    // layer 1: H1 = x @ W (per head), scores, aggregate+elu -> XC
    dim3 g1((N_NODES + 127) / 128, NHEADS);
    k_gemm<<<g1, 256>>>(x, W, pH1, N_NODES, F_INF, D1);
    k_scores1<<<N_NODES, 256>>>(a);
    k_agg1<<<N_NODES, 128>>>();

    // layer 2: H2 = XC @ Wo, scores, aggregate+elu -> XO
    dim3 g2((N_NODES + 127) / 128, 1);
    k_gemm<<<g2, 256>>>(pXC, Wo, pH2, N_NODES, D1, FH);
    k_scores2<<<(N_NODES + 7) / 8, 256>>>(ao);
    k_agg2<<<N_NODES, 64>>>();

    // classifier
    k_final<<<(N_NODES * NCLASSF + 255) / 256, 256>>>(mw, mb, out);
}

// round 4
// speedup vs baseline: 1.2050x; 1.2050x over previous
#include <cuda_runtime.h>
#include <cuda_bf16.h>
#include <cstdint>

#define N_NODES 50000
#define N_EDGES 850000
#define F_INF   256
#define FH      64
#define NHEADS  8
#define NCLASSF 40
#define ALPHAF  0.2f
#define D1      (NHEADS * FH)   // 512

// ---------------- device scratch ----------------
__device__ float g_H1[(size_t)N_NODES * D1];
__device__ float g_S1s[N_NODES * NHEADS];
__device__ float g_S1d[N_NODES * NHEADS];
__device__ float g_H2[(size_t)N_NODES * FH];
__device__ float g_XO[(size_t)N_NODES * FH];
__device__ float g_S2s[N_NODES];
__device__ float g_S2d[N_NODES];
__device__ int   g_rowptr[N_NODES + 1];
__device__ int   g_cnt[N_NODES];
__device__ int   g_pos[N_NODES];
__device__ int   g_dsts[N_EDGES];
// bf16 split operands
__device__ __nv_bfloat16 g_xh[(size_t)N_NODES * F_INF];
__device__ __nv_bfloat16 g_xl[(size_t)N_NODES * F_INF];
__device__ __nv_bfloat16 g_wth[NHEADS * FH * F_INF];
__device__ __nv_bfloat16 g_wtl[NHEADS * FH * F_INF];
__device__ __nv_bfloat16 g_woth[FH * D1];
__device__ __nv_bfloat16 g_wotl[FH * D1];
__device__ __nv_bfloat16 g_xch[(size_t)N_NODES * D1];
__device__ __nv_bfloat16 g_xcl[(size_t)N_NODES * D1];

__device__ __forceinline__ float leakyv(float v) { return v > 0.f ? v : ALPHAF * v; }
__device__ __forceinline__ float eluv(float v)   { return v > 0.f ? v : expm1f(v); }

// ---------------- CSR build ----------------
__global__ void k_zero_cnt() {
    int i = blockIdx.x * blockDim.x + threadIdx.x;
    if (i < N_NODES) g_cnt[i] = 0;
}
__global__ void k_hist(const int* __restrict__ src) {
    int e = blockIdx.x * blockDim.x + threadIdx.x;
    if (e < N_EDGES) atomicAdd(&g_cnt[src[e]], 1);
}
__global__ __launch_bounds__(1024) void k_scan() {
    __shared__ int s[1024];
    const int CH = 49;
    int t = threadIdx.x;
    int start = t * CH;
    int end = start + CH; if (end > N_NODES) end = N_NODES;
    int sum = 0;
    for (int i = start; i < end; i++) sum += g_cnt[i];
    s[t] = sum;
    __syncthreads();
    for (int off = 1; off < 1024; off <<= 1) {
        int v = (t >= off) ? s[t - off] : 0;
        __syncthreads();
        s[t] += v;
        __syncthreads();
    }
    int run = (t == 0) ? 0 : s[t - 1];
    for (int i = start; i < end; i++) {
        g_rowptr[i] = run;
        g_pos[i] = run;
        run += g_cnt[i];
    }
    if (t == 0) g_rowptr[N_NODES] = s[1023];
}
__global__ void k_scatter(const int* __restrict__ src, const int* __restrict__ dst) {
    int e = blockIdx.x * blockDim.x + threadIdx.x;
    if (e < N_EDGES) {
        int p = atomicAdd(&g_pos[src[e]], 1);
        g_dsts[p] = dst[e];
    }
}

// ---------------- bf16 hi/lo splits ----------------
__global__ void k_split_x(const float* __restrict__ x, __nv_bfloat16* __restrict__ oh,
                          __nv_bfloat16* __restrict__ ol, int n4) {
    int i = blockIdx.x * blockDim.x + threadIdx.x;
    if (i >= n4) return;
    float4 v = ((const float4*)x)[i];
    __nv_bfloat16 h0 = __float2bfloat16(v.x), h1 = __float2bfloat16(v.y);
    __nv_bfloat16 h2 = __float2bfloat16(v.z), h3 = __float2bfloat16(v.w);
    __nv_bfloat16 l0 = __float2bfloat16(v.x - __bfloat162float(h0));
    __nv_bfloat16 l1 = __float2bfloat16(v.y - __bfloat162float(h1));
    __nv_bfloat16 l2 = __float2bfloat16(v.z - __bfloat162float(h2));
    __nv_bfloat16 l3 = __float2bfloat16(v.w - __bfloat162float(h3));
    __nv_bfloat162* ph = (__nv_bfloat162*)(oh) + i * 2;
    __nv_bfloat162* pl = (__nv_bfloat162*)(ol) + i * 2;
    ph[0] = __halves2bfloat162(h0, h1); ph[1] = __halves2bfloat162(h2, h3);
    pl[0] = __halves2bfloat162(l0, l1); pl[1] = __halves2bfloat162(l2, l3);
}
// W[h][k][n] (fp32) -> out[h][n][k] bf16 hi/lo
__global__ void k_split_wt(const float* __restrict__ W, __nv_bfloat16* __restrict__ oh,
                           __nv_bfloat16* __restrict__ ol) {
    int i = blockIdx.x * blockDim.x + threadIdx.x;
    if (i >= NHEADS * F_INF * FH) return;
    int h = i / (F_INF * FH), r = i % (F_INF * FH), k = r / FH, n = r % FH;
    float v = W[i];
    __nv_bfloat16 hh = __float2bfloat16(v);
    __nv_bfloat16 ll = __float2bfloat16(v - __bfloat162float(hh));
    size_t o = (size_t)(h * FH + n) * F_INF + k;
    oh[o] = hh; ol[o] = ll;
}
// Wo[k][n] -> out[n][k]
__global__ void k_split_wot(const float* __restrict__ Wo, __nv_bfloat16* __restrict__ oh,
                            __nv_bfloat16* __restrict__ ol) {
    int i = blockIdx.x * blockDim.x + threadIdx.x;
    if (i >= D1 * FH) return;
    int k = i / FH, n = i % FH;
    float v = Wo[i];
    __nv_bfloat16 hh = __float2bfloat16(v);
    __nv_bfloat16 ll = __float2bfloat16(v - __bfloat162float(hh));
    size_t o = (size_t)n * D1 + k;
    oh[o] = hh; ol[o] = ll;
}

// ---------------- mma.sync bf16x3 GEMM with fused score epilogue ----------
// C tile [128, 64] = A[128, K] @ B[64, K]^T, A/B as bf16 hi/lo (3-term split).
// blockIdx.y selects B sub-matrix (head) of shape [64][K] and score column.
#define BM 128
#define BN 64
#define BK 32
#define AST 40   // padded row stride in bf16 (80B -> conflict-free fragments)

__device__ __forceinline__ void mma16816(float* d, const uint32_t* a, const uint32_t* b) {
    asm volatile(
        "mma.sync.aligned.m16n8k16.row.col.f32.bf16.bf16.f32 "
        "{%0,%1,%2,%3},{%4,%5,%6,%7},{%8,%9},{%0,%1,%2,%3};"
        : "+f"(d[0]), "+f"(d[1]), "+f"(d[2]), "+f"(d[3])
        : "r"(a[0]), "r"(a[1]), "r"(a[2]), "r"(a[3]), "r"(b[0]), "r"(b[1]));
}

__global__ __launch_bounds__(256) void k_gemm_mma(
    const __nv_bfloat16* __restrict__ Ah, const __nv_bfloat16* __restrict__ Al,
    const __nv_bfloat16* __restrict__ Bh, const __nv_bfloat16* __restrict__ Bl,
    int M, int K, float* __restrict__ C, int ldc,
    const float* __restrict__ att, float* __restrict__ Ss, float* __restrict__ Sd,
    int sstride)
{
    __shared__ alignas(16) __nv_bfloat16 sAh[BM * AST];
    __shared__ alignas(16) __nv_bfloat16 sAl[BM * AST];
    __shared__ alignas(16) __nv_bfloat16 sBh[BN * AST];
    __shared__ alignas(16) __nv_bfloat16 sBl[BN * AST];
    __shared__ float red[2][BM][2];

    int tid = threadIdx.x, lane = tid & 31, wid = tid >> 5;
    int wm = wid & 3, wn = wid >> 2;          // warp grid 4(m) x 2(n)
    int m0 = blockIdx.x * BM;
    int bidy = blockIdx.y;
    Bh += (size_t)bidy * FH * K;
    Bl += (size_t)bidy * FH * K;
    att += bidy * 2 * FH;
    int coloff = bidy * FH;

    float acc[2][4][4];
#pragma unroll
    for (int i = 0; i < 2; i++)
#pragma unroll
        for (int j = 0; j < 4; j++)
#pragma unroll
            for (int l = 0; l < 4; l++) acc[i][j][l] = 0.f;

    int q = lane >> 2, cq = (lane & 3) * 2;

    for (int k0 = 0; k0 < K; k0 += BK) {
        // ---- stage tiles: 1536 uint4 (A hi/lo 512 each, B hi/lo 256 each) ----
#pragma unroll
        for (int l = 0; l < 6; l++) {
            int it = tid + l * 256;
            uint4 v = make_uint4(0u, 0u, 0u, 0u);
            __nv_bfloat16* dsts;
            if (it < 1024) {
                int p = it >> 9, i = it & 511;
                int row = i >> 2, qq = i & 3;
                const __nv_bfloat16* s = p ? Al : Ah;
                if (m0 + row < M)
                    v = *(const uint4*)(s + (size_t)(m0 + row) * K + k0 + qq * 8);
                dsts = (p ? sAl : sAh) + row * AST + qq * 8;
            } else {
                int j = it - 1024, p = j >> 8, i = j & 255;
                int row = i >> 2, qq = i & 3;
                const __nv_bfloat16* s = p ? Bl : Bh;
                v = *(const uint4*)(s + (size_t)row * K + k0 + qq * 8);
                dsts = (p ? sBl : sBh) + row * AST + qq * 8;
            }
            *(uint4*)dsts = v;
        }
        __syncthreads();

#pragma unroll
        for (int kf = 0; kf < 2; kf++) {
            int c0 = kf * 16 + cq;
            uint32_t ah[2][4], al[2][4], bh[4][2], bl[4][2];
#pragma unroll
            for (int mf = 0; mf < 2; mf++) {
                int r = wm * 32 + mf * 16 + q;
                ah[mf][0] = *(const uint32_t*)&sAh[r * AST + c0];
                ah[mf][1] = *(const uint32_t*)&sAh[(r + 8) * AST + c0];
                ah[mf][2] = *(const uint32_t*)&sAh[r * AST + c0 + 8];
                ah[mf][3] = *(const uint32_t*)&sAh[(r + 8) * AST + c0 + 8];
                al[mf][0] = *(const uint32_t*)&sAl[r * AST + c0];
                al[mf][1] = *(const uint32_t*)&sAl[(r + 8) * AST + c0];
                al[mf][2] = *(const uint32_t*)&sAl[r * AST + c0 + 8];
                al[mf][3] = *(const uint32_t*)&sAl[(r + 8) * AST + c0 + 8];
            }
#pragma unroll
            for (int nf = 0; nf < 4; nf++) {
                int n = wn * 32 + nf * 8 + q;
                bh[nf][0] = *(const uint32_t*)&sBh[n * AST + c0];
                bh[nf][1] = *(const uint32_t*)&sBh[n * AST + c0 + 8];
                bl[nf][0] = *(const uint32_t*)&sBl[n * AST + c0];
                bl[nf][1] = *(const uint32_t*)&sBl[n * AST + c0 + 8];
            }
#pragma unroll
            for (int mf = 0; mf < 2; mf++)
#pragma unroll
                for (int nf = 0; nf < 4; nf++) {
                    mma16816(acc[mf][nf], ah[mf], bh[nf]);
                    mma16816(acc[mf][nf], ah[mf], bl[nf]);
                    mma16816(acc[mf][nf], al[mf], bh[nf]);
                }
        }
        __syncthreads();
    }

    // ---- epilogue: store C, fused score dot products ----
    float sp[2][2][2];  // [mf][rowhalf][score]
#pragma unroll
    for (int mf = 0; mf < 2; mf++)
#pragma unroll
        for (int h = 0; h < 2; h++) { sp[mf][h][0] = 0.f; sp[mf][h][1] = 0.f; }

#pragma unroll
    for (int mf = 0; mf < 2; mf++) {
        int r = wm * 32 + mf * 16 + q;
        int mr = m0 + r;
#pragma unroll
        for (int nf = 0; nf < 4; nf++) {
            int c = wn * 32 + nf * 8 + cq;
            float d0 = acc[mf][nf][0], d1 = acc[mf][nf][1];
            float d2 = acc[mf][nf][2], d3 = acc[mf][nf][3];
            if (mr < M) *(float2*)&C[(size_t)mr * ldc + coloff + c] = make_float2(d0, d1);
            if (mr + 8 < M) *(float2*)&C[(size_t)(mr + 8) * ldc + coloff + c] = make_float2(d2, d3);
            float a0 = att[c], a1 = att[c + 1], a2 = att[FH + c], a3 = att[FH + c + 1];
            sp[mf][0][0] = fmaf(d0, a0, fmaf(d1, a1, sp[mf][0][0]));
            sp[mf][0][1] = fmaf(d0, a2, fmaf(d1, a3, sp[mf][0][1]));
            sp[mf][1][0] = fmaf(d2, a0, fmaf(d3, a1, sp[mf][1][0]));
            sp[mf][1][1] = fmaf(d2, a2, fmaf(d3, a3, sp[mf][1][1]));
        }
    }
    // quad reduce (cols live in lane&3)
#pragma unroll
    for (int mf = 0; mf < 2; mf++)
#pragma unroll
        for (int h = 0; h < 2; h++)
#pragma unroll
            for (int sc = 0; sc < 2; sc++) {
                float v = sp[mf][h][sc];
                v += __shfl_xor_sync(0xffffffffu, v, 1);
                v += __shfl_xor_sync(0xffffffffu, v, 2);
                sp[mf][h][sc] = v;
            }
    if ((lane & 3) == 0) {
#pragma unroll
        for (int mf = 0; mf < 2; mf++)
#pragma unroll
            for (int h = 0; h < 2; h++) {
                int r = wm * 32 + mf * 16 + q + h * 8;
                red[wn][r][0] = sp[mf][h][0];
                red[wn][r][1] = sp[mf][h][1];
            }
    }
    __syncthreads();
    if (tid < BM) {
        int m = m0 + tid;
        if (m < M) {
            Ss[(size_t)m * sstride + bidy] = red[0][tid][0] + red[1][tid][0];
            Sd[(size_t)m * sstride + bidy] = red[0][tid][1] + red[1][tid][1];
        }
    }
}

// ---------------- layer-1 aggregation (8 heads fused) -> bf16 split XC -----
__global__ __launch_bounds__(128) void k_agg1() {
    int n = blockIdx.x, t = threadIdx.x;
    int head = t >> 4;
    float ss = g_S1s[n * NHEADS + head];
    float4 acc = make_float4(0.f, 0.f, 0.f, 0.f);
    float rs = 0.f;
    int beg = g_rowptr[n], end = g_rowptr[n + 1];
    for (int e = beg; e < end; e++) {
        int d = g_dsts[e];
        float v = ss + g_S1d[d * NHEADS + head];
        float wgt = __expf(-leakyv(v));
        float4 hv = *(const float4*)&g_H1[(size_t)d * D1 + t * 4];
        acc.x = fmaf(wgt, hv.x, acc.x);
        acc.y = fmaf(wgt, hv.y, acc.y);
        acc.z = fmaf(wgt, hv.z, acc.z);
        acc.w = fmaf(wgt, hv.w, acc.w);
        rs += wgt;
    }
    float inv = 1.f / rs;
    float o[4] = { eluv(acc.x * inv), eluv(acc.y * inv), eluv(acc.z * inv), eluv(acc.w * inv) };
    size_t base = (size_t)n * D1 + t * 4;
    __nv_bfloat16 hh[4], ll[4];
#pragma unroll
    for (int j = 0; j < 4; j++) {
        hh[j] = __float2bfloat16(o[j]);
        ll[j] = __float2bfloat16(o[j] - __bfloat162float(hh[j]));
    }
    __nv_bfloat162* ph = (__nv_bfloat162*)&g_xch[base];
    __nv_bfloat162* pl = (__nv_bfloat162*)&g_xcl[base];
    ph[0] = __halves2bfloat162(hh[0], hh[1]); ph[1] = __halves2bfloat162(hh[2], hh[3]);
    pl[0] = __halves2bfloat162(ll[0], ll[1]); pl[1] = __halves2bfloat162(ll[2], ll[3]);
}

// ---------------- layer-2 aggregation ----------------
__global__ __launch_bounds__(64) void k_agg2() {
    int n = blockIdx.x, t = threadIdx.x;
    float ss = g_S2s[n];
    float acc = 0.f, rs = 0.f;
    int beg = g_rowptr[n], end = g_rowptr[n + 1];
    for (int e = beg; e < end; e++) {
        int d = g_dsts[e];
        float v = ss + g_S2d[d];
        float wgt = __expf(-leakyv(v));
        acc = fmaf(wgt, g_H2[(size_t)d * FH + t], acc);
        rs += wgt;
    }
    g_XO[(size_t)n * FH + t] = eluv(acc / rs);
}

// ---------------- final classifier ----------------
__global__ __launch_bounds__(256) void k_final(const float* __restrict__ mw,
                                               const float* __restrict__ mb,
                                               float* __restrict__ out) {
    int idx = blockIdx.x * blockDim.x + threadIdx.x;
    if (idx >= N_NODES * NCLASSF) return;
    int n = idx / NCLASSF, c = idx - n * NCLASSF;
    const float* xo = &g_XO[(size_t)n * FH];
    const float* wv = &mw[c * FH];
    float s = mb[c];
#pragma unroll
    for (int k = 0; k < FH; k++) s = fmaf(xo[k], wv[k], s);
    out[idx] = s;
}

// ---------------- launch ----------------
extern "C" void kernel_launch(void* const* d_in, const int* in_sizes, int n_in,
                              void* d_out, int out_size) {
    const float* x  = (const float*)d_in[0];
    const int*   ei = (const int*)d_in[1];
    const float* W  = (const float*)d_in[2];
    const float* a  = (const float*)d_in[3];
    const float* Wo = (const float*)d_in[4];
    const float* ao = (const float*)d_in[5];
    const float* mw = (const float*)d_in[6];
    const float* mb = (const float*)d_in[7];
    float* out = (float*)d_out;

    const int* src = ei;
    const int* dst = ei + N_EDGES;

    float *pH1, *pH2, *pS1s, *pS1d, *pS2s, *pS2d;
    __nv_bfloat16 *pxh, *pxl, *pwth, *pwtl, *pwoth, *pwotl, *pxch, *pxcl;
    cudaGetSymbolAddress((void**)&pH1, g_H1);
    cudaGetSymbolAddress((void**)&pH2, g_H2);
    cudaGetSymbolAddress((void**)&pS1s, g_S1s);
    cudaGetSymbolAddress((void**)&pS1d, g_S1d);
    cudaGetSymbolAddress((void**)&pS2s, g_S2s);
    cudaGetSymbolAddress((void**)&pS2d, g_S2d);
    cudaGetSymbolAddress((void**)&pxh, g_xh);
    cudaGetSymbolAddress((void**)&pxl, g_xl);
    cudaGetSymbolAddress((void**)&pwth, g_wth);
    cudaGetSymbolAddress((void**)&pwtl, g_wtl);
    cudaGetSymbolAddress((void**)&pwoth, g_woth);
    cudaGetSymbolAddress((void**)&pwotl, g_wotl);
    cudaGetSymbolAddress((void**)&pxch, g_xch);
    cudaGetSymbolAddress((void**)&pxcl, g_xcl);

    // CSR build
    k_zero_cnt<<<(N_NODES + 255) / 256, 256>>>();
    k_hist<<<(N_EDGES + 255) / 256, 256>>>(src);
    k_scan<<<1, 1024>>>();
    k_scatter<<<(N_EDGES + 255) / 256, 256>>>(src, dst);

    // operand splits
    k_split_x<<<(N_NODES * F_INF / 4 + 255) / 256, 256>>>(x, pxh, pxl, N_NODES * F_INF / 4);
    k_split_wt<<<(NHEADS * F_INF * FH + 255) / 256, 256>>>(W, pwth, pwtl);
    k_split_wot<<<(D1 * FH + 255) / 256, 256>>>(Wo, pwoth, pwotl);

    // layer 1: H1 = x @ W per head (mma.sync bf16x3) + fused scores
    dim3 g1((N_NODES + BM - 1) / BM, NHEADS);
    k_gemm_mma<<<g1, 256>>>(pxh, pxl, pwth, pwtl, N_NODES, F_INF,
                            pH1, D1, a, pS1s, pS1d, NHEADS);
    k_agg1<<<N_NODES, 128>>>();

    // layer 2: H2 = XC @ Wo (mma.sync bf16x3) + fused scores
    dim3 g2((N_NODES + BM - 1) / BM, 1);
    k_gemm_mma<<<g2, 256>>>(pxch, pxcl, pwoth, pwotl, N_NODES, D1,
                            pH2, FH, ao, pS2s, pS2d, 1);
    k_agg2<<<N_NODES, 64>>>();

    // classifier
    k_final<<<(N_NODES * NCLASSF + 255) / 256, 256>>>(mw, mb, out);
}

// round 5
// speedup vs baseline: 1.9245x; 1.5971x over previous
#include <cuda_runtime.h>
#include <cuda_bf16.h>
#include <cstdint>

#define N_NODES 50000
#define N_EDGES 850000
#define F_INF   256
#define FH      64
#define NHEADS  8
#define NCLASSF 40
#define ALPHAF  0.2f
#define D1      (NHEADS * FH)   // 512

// ---------------- device scratch ----------------
__device__ float g_H1[(size_t)N_NODES * D1];
__device__ float g_S1s[N_NODES * NHEADS];
__device__ float g_S1d[N_NODES * NHEADS];
__device__ float g_H2[(size_t)N_NODES * FH];
__device__ float g_XO[(size_t)N_NODES * FH];
__device__ float g_S2s[N_NODES];
__device__ float g_S2d[N_NODES];
__device__ int   g_rowptr[N_NODES + 1];
__device__ int   g_cnt[N_NODES];
__device__ int   g_pos[N_NODES];
__device__ int   g_dsts[N_EDGES];
// bf16 split operands
__device__ __nv_bfloat16 g_xh[(size_t)N_NODES * F_INF];
__device__ __nv_bfloat16 g_xl[(size_t)N_NODES * F_INF];
__device__ __nv_bfloat16 g_wth[NHEADS * FH * F_INF];
__device__ __nv_bfloat16 g_wtl[NHEADS * FH * F_INF];
__device__ __nv_bfloat16 g_woth[FH * D1];
__device__ __nv_bfloat16 g_wotl[FH * D1];
__device__ __nv_bfloat16 g_xch[(size_t)N_NODES * D1];
__device__ __nv_bfloat16 g_xcl[(size_t)N_NODES * D1];

__device__ __forceinline__ float leakyv(float v) { return v > 0.f ? v : ALPHAF * v; }
__device__ __forceinline__ float eluv(float v)   { return v > 0.f ? v : expm1f(v); }

// ---------------- CSR build ----------------
__global__ void k_zero_cnt() {
    int i = blockIdx.x * blockDim.x + threadIdx.x;
    if (i < N_NODES) g_cnt[i] = 0;
}
__global__ void k_hist(const int* __restrict__ src) {
    int e = blockIdx.x * blockDim.x + threadIdx.x;
    if (e < N_EDGES) atomicAdd(&g_cnt[src[e]], 1);
}
__global__ __launch_bounds__(1024) void k_scan() {
    __shared__ int s[1024];
    const int CH = 49;
    int t = threadIdx.x;
    int start = t * CH;
    int end = start + CH; if (end > N_NODES) end = N_NODES;
    int sum = 0;
    for (int i = start; i < end; i++) sum += g_cnt[i];
    s[t] = sum;
    __syncthreads();
    for (int off = 1; off < 1024; off <<= 1) {
        int v = (t >= off) ? s[t - off] : 0;
        __syncthreads();
        s[t] += v;
        __syncthreads();
    }
    int run = (t == 0) ? 0 : s[t - 1];
    for (int i = start; i < end; i++) {
        g_rowptr[i] = run;
        g_pos[i] = run;
        run += g_cnt[i];
    }
    if (t == 0) g_rowptr[N_NODES] = s[1023];
}
__global__ void k_scatter(const int* __restrict__ src, const int* __restrict__ dst) {
    int e = blockIdx.x * blockDim.x + threadIdx.x;
    if (e < N_EDGES) {
        int p = atomicAdd(&g_pos[src[e]], 1);
        g_dsts[p] = dst[e];
    }
}

// ---------------- bf16 hi/lo splits ----------------
__global__ void k_split_x(const float* __restrict__ x, __nv_bfloat16* __restrict__ oh,
                          __nv_bfloat16* __restrict__ ol, int n4) {
    int i = blockIdx.x * blockDim.x + threadIdx.x;
    if (i >= n4) return;
    float4 v = ((const float4*)x)[i];
    __nv_bfloat16 h0 = __float2bfloat16(v.x), h1 = __float2bfloat16(v.y);
    __nv_bfloat16 h2 = __float2bfloat16(v.z), h3 = __float2bfloat16(v.w);
    __nv_bfloat16 l0 = __float2bfloat16(v.x - __bfloat162float(h0));
    __nv_bfloat16 l1 = __float2bfloat16(v.y - __bfloat162float(h1));
    __nv_bfloat16 l2 = __float2bfloat16(v.z - __bfloat162float(h2));
    __nv_bfloat16 l3 = __float2bfloat16(v.w - __bfloat162float(h3));
    __nv_bfloat162* ph = (__nv_bfloat162*)(oh) + i * 2;
    __nv_bfloat162* pl = (__nv_bfloat162*)(ol) + i * 2;
    ph[0] = __halves2bfloat162(h0, h1); ph[1] = __halves2bfloat162(h2, h3);
    pl[0] = __halves2bfloat162(l0, l1); pl[1] = __halves2bfloat162(l2, l3);
}
// W[h][k][n] (fp32) -> out[h][n][k] bf16 hi/lo
__global__ void k_split_wt(const float* __restrict__ W, __nv_bfloat16* __restrict__ oh,
                           __nv_bfloat16* __restrict__ ol) {
    int i = blockIdx.x * blockDim.x + threadIdx.x;
    if (i >= NHEADS * F_INF * FH) return;
    int h = i / (F_INF * FH), r = i % (F_INF * FH), k = r / FH, n = r % FH;
    float v = W[i];
    __nv_bfloat16 hh = __float2bfloat16(v);
    __nv_bfloat16 ll = __float2bfloat16(v - __bfloat162float(hh));
    size_t o = (size_t)(h * FH + n) * F_INF + k;
    oh[o] = hh; ol[o] = ll;
}
// Wo[k][n] -> out[n][k]
__global__ void k_split_wot(const float* __restrict__ Wo, __nv_bfloat16* __restrict__ oh,
                            __nv_bfloat16* __restrict__ ol) {
    int i = blockIdx.x * blockDim.x + threadIdx.x;
    if (i >= D1 * FH) return;
    int k = i / FH, n = i % FH;
    float v = Wo[i];
    __nv_bfloat16 hh = __float2bfloat16(v);
    __nv_bfloat16 ll = __float2bfloat16(v - __bfloat162float(hh));
    size_t o = (size_t)n * D1 + k;
    oh[o] = hh; ol[o] = ll;
}

// ---------------- mma.sync bf16x3 GEMM with fused score epilogue ----------
#define BM 128
#define BN 64
#define BK 32
#define AST 40   // padded row stride in bf16 (80B)

__device__ __forceinline__ void mma16816(float* d, const uint32_t* a, const uint32_t* b) {
    asm volatile(
        "mma.sync.aligned.m16n8k16.row.col.f32.bf16.bf16.f32 "
        "{%0,%1,%2,%3},{%4,%5,%6,%7},{%8,%9},{%0,%1,%2,%3};"
        : "+f"(d[0]), "+f"(d[1]), "+f"(d[2]), "+f"(d[3])
        : "r"(a[0]), "r"(a[1]), "r"(a[2]), "r"(a[3]), "r"(b[0]), "r"(b[1]));
}
__device__ __forceinline__ void ldsm4(uint32_t* r, const void* p) {
    uint32_t addr = (uint32_t)__cvta_generic_to_shared(p);
    asm volatile("ldmatrix.sync.aligned.m8n8.x4.shared.b16 {%0,%1,%2,%3}, [%4];"
                 : "=r"(r[0]), "=r"(r[1]), "=r"(r[2]), "=r"(r[3]) : "r"(addr));
}

__global__ __launch_bounds__(256) void k_gemm_mma(
    const __nv_bfloat16* __restrict__ Ah, const __nv_bfloat16* __restrict__ Al,
    const __nv_bfloat16* __restrict__ Bh, const __nv_bfloat16* __restrict__ Bl,
    int M, int K, float* __restrict__ C, int ldc,
    const float* __restrict__ att, float* __restrict__ Ss, float* __restrict__ Sd,
    int sstride)
{
    __shared__ alignas(16) __nv_bfloat16 sAh[BM * AST];
    __shared__ alignas(16) __nv_bfloat16 sAl[BM * AST];
    __shared__ alignas(16) __nv_bfloat16 sBh[BN * AST];
    __shared__ alignas(16) __nv_bfloat16 sBl[BN * AST];
    __shared__ float red[2][BM][2];

    int tid = threadIdx.x, lane = tid & 31, wid = tid >> 5;
    int wm = wid & 3, wn = wid >> 2;          // warp grid 4(m) x 2(n)
    int m0 = blockIdx.x * BM;
    int bidy = blockIdx.y;
    Bh += (size_t)bidy * FH * K;
    Bl += (size_t)bidy * FH * K;
    att += bidy * 2 * FH;
    int coloff = bidy * FH;

    float acc[2][4][4];
#pragma unroll
    for (int i = 0; i < 2; i++)
#pragma unroll
        for (int j = 0; j < 4; j++)
#pragma unroll
            for (int l = 0; l < 4; l++) acc[i][j][l] = 0.f;

    int q = lane >> 2, cq = (lane & 3) * 2;

    // precomputed per-thread staging indices (6 items of 16B each)
    int st_row[6], st_q[6], st_sel[6];  // sel: 0 Ah,1 Al,2 Bh,3 Bl
#pragma unroll
    for (int l = 0; l < 6; l++) {
        int it = tid + l * 256;
        if (it < 1024) {
            int p = it >> 9, i = it & 511;
            st_sel[l] = p; st_row[l] = i >> 2; st_q[l] = i & 3;
        } else {
            int j = it - 1024, p = j >> 8, i = j & 255;
            st_sel[l] = 2 + p; st_row[l] = i >> 2; st_q[l] = i & 3;
        }
    }

    uint4 pf[6];
    auto load_tile = [&](int k0) {
#pragma unroll
        for (int l = 0; l < 6; l++) {
            uint4 v = make_uint4(0u, 0u, 0u, 0u);
            int row = st_row[l], qq = st_q[l];
            switch (st_sel[l]) {
                case 0: if (m0 + row < M) v = *(const uint4*)(Ah + (size_t)(m0 + row) * K + k0 + qq * 8); break;
                case 1: if (m0 + row < M) v = *(const uint4*)(Al + (size_t)(m0 + row) * K + k0 + qq * 8); break;
                case 2: v = *(const uint4*)(Bh + (size_t)row * K + k0 + qq * 8); break;
                default: v = *(const uint4*)(Bl + (size_t)row * K + k0 + qq * 8); break;
            }
            pf[l] = v;
        }
    };
    auto store_tile = [&]() {
#pragma unroll
        for (int l = 0; l < 6; l++) {
            int row = st_row[l], qq = st_q[l];
            __nv_bfloat16* d;
            switch (st_sel[l]) {
                case 0: d = sAh + row * AST + qq * 8; break;
                case 1: d = sAl + row * AST + qq * 8; break;
                case 2: d = sBh + row * AST + qq * 8; break;
                default: d = sBl + row * AST + qq * 8; break;
            }
            *(uint4*)d = pf[l];
        }
    };

    load_tile(0);
    store_tile();
    __syncthreads();

    int arow = lane & 15, ak = (lane >> 4) * 8;
    int brow = (lane & 7) + ((lane >> 4) << 3), bk = ((lane >> 3) & 1) * 8;

    for (int k0 = 0; k0 < K; k0 += BK) {
        bool has_next = (k0 + BK) < K;
        if (has_next) load_tile(k0 + BK);   // gmem -> regs, overlapped with MMAs

#pragma unroll
        for (int kf = 0; kf < 2; kf++) {
            int c0 = kf * 16;
            uint32_t ah[2][4], al[2][4], bhf[4][2], blf[4][2];
#pragma unroll
            for (int mf = 0; mf < 2; mf++) {
                int r = (wm * 32 + mf * 16 + arow) * AST + c0 + ak;
                ldsm4(ah[mf], &sAh[r]);
                ldsm4(al[mf], &sAl[r]);
            }
#pragma unroll
            for (int nfp = 0; nfp < 2; nfp++) {
                int r = (wn * 32 + nfp * 16 + brow) * AST + c0 + bk;
                uint32_t tb[4], tl[4];
                ldsm4(tb, &sBh[r]);
                ldsm4(tl, &sBl[r]);
                bhf[2 * nfp][0] = tb[0]; bhf[2 * nfp][1] = tb[1];
                bhf[2 * nfp + 1][0] = tb[2]; bhf[2 * nfp + 1][1] = tb[3];
                blf[2 * nfp][0] = tl[0]; blf[2 * nfp][1] = tl[1];
                blf[2 * nfp + 1][0] = tl[2]; blf[2 * nfp + 1][1] = tl[3];
            }
#pragma unroll
            for (int mf = 0; mf < 2; mf++)
#pragma unroll
                for (int nf = 0; nf < 4; nf++) {
                    mma16816(acc[mf][nf], ah[mf], bhf[nf]);
                    mma16816(acc[mf][nf], ah[mf], blf[nf]);
                    mma16816(acc[mf][nf], al[mf], bhf[nf]);
                }
        }
        __syncthreads();
        if (has_next) {
            store_tile();
            __syncthreads();
        }
    }

    // ---- epilogue: store C, fused score dot products ----
    float sp[2][2][2];
#pragma unroll
    for (int mf = 0; mf < 2; mf++)
#pragma unroll
        for (int h = 0; h < 2; h++) { sp[mf][h][0] = 0.f; sp[mf][h][1] = 0.f; }

#pragma unroll
    for (int mf = 0; mf < 2; mf++) {
        int r = wm * 32 + mf * 16 + q;
        int mr = m0 + r;
#pragma unroll
        for (int nf = 0; nf < 4; nf++) {
            int c = wn * 32 + nf * 8 + cq;
            float d0 = acc[mf][nf][0], d1 = acc[mf][nf][1];
            float d2 = acc[mf][nf][2], d3 = acc[mf][nf][3];
            if (mr < M) *(float2*)&C[(size_t)mr * ldc + coloff + c] = make_float2(d0, d1);
            if (mr + 8 < M) *(float2*)&C[(size_t)(mr + 8) * ldc + coloff + c] = make_float2(d2, d3);
            float a0 = att[c], a1 = att[c + 1], a2 = att[FH + c], a3 = att[FH + c + 1];
            sp[mf][0][0] = fmaf(d0, a0, fmaf(d1, a1, sp[mf][0][0]));
            sp[mf][0][1] = fmaf(d0, a2, fmaf(d1, a3, sp[mf][0][1]));
            sp[mf][1][0] = fmaf(d2, a0, fmaf(d3, a1, sp[mf][1][0]));
            sp[mf][1][1] = fmaf(d2, a2, fmaf(d3, a3, sp[mf][1][1]));
        }
    }
#pragma unroll
    for (int mf = 0; mf < 2; mf++)
#pragma unroll
        for (int h = 0; h < 2; h++)
#pragma unroll
            for (int sc = 0; sc < 2; sc++) {
                float v = sp[mf][h][sc];
                v += __shfl_xor_sync(0xffffffffu, v, 1);
                v += __shfl_xor_sync(0xffffffffu, v, 2);
                sp[mf][h][sc] = v;
            }
    if ((lane & 3) == 0) {
#pragma unroll
        for (int mf = 0; mf < 2; mf++)
#pragma unroll
            for (int h = 0; h < 2; h++) {
                int r = wm * 32 + mf * 16 + q + h * 8;
                red[wn][r][0] = sp[mf][h][0];
                red[wn][r][1] = sp[mf][h][1];
            }
    }
    __syncthreads();
    if (tid < BM) {
        int m = m0 + tid;
        if (m < M) {
            Ss[(size_t)m * sstride + bidy] = red[0][tid][0] + red[1][tid][0];
            Sd[(size_t)m * sstride + bidy] = red[0][tid][1] + red[1][tid][1];
        }
    }
}

// ---------------- layer-1 aggregation (8 heads fused) -> bf16 split XC -----
__global__ __launch_bounds__(128) void k_agg1() {
    int n = blockIdx.x, t = threadIdx.x;
    int head = t >> 4;
    float ss = g_S1s[n * NHEADS + head];
    float4 acc0 = make_float4(0.f, 0.f, 0.f, 0.f);
    float4 acc1 = make_float4(0.f, 0.f, 0.f, 0.f);
    float rs0 = 0.f, rs1 = 0.f;
    int beg = g_rowptr[n], end = g_rowptr[n + 1];
    int e = beg;
    for (; e + 1 < end; e += 2) {
        int d0 = g_dsts[e], d1 = g_dsts[e + 1];
        float sd0 = g_S1d[d0 * NHEADS + head];
        float sd1 = g_S1d[d1 * NHEADS + head];
        float4 h0 = *(const float4*)&g_H1[(size_t)d0 * D1 + t * 4];
        float4 h1 = *(const float4*)&g_H1[(size_t)d1 * D1 + t * 4];
        float w0 = __expf(-leakyv(ss + sd0));
        float w1 = __expf(-leakyv(ss + sd1));
        acc0.x = fmaf(w0, h0.x, acc0.x); acc0.y = fmaf(w0, h0.y, acc0.y);
        acc0.z = fmaf(w0, h0.z, acc0.z); acc0.w = fmaf(w0, h0.w, acc0.w);
        acc1.x = fmaf(w1, h1.x, acc1.x); acc1.y = fmaf(w1, h1.y, acc1.y);
        acc1.z = fmaf(w1, h1.z, acc1.z); acc1.w = fmaf(w1, h1.w, acc1.w);
        rs0 += w0; rs1 += w1;
    }
    if (e < end) {
        int d0 = g_dsts[e];
        float sd0 = g_S1d[d0 * NHEADS + head];
        float4 h0 = *(const float4*)&g_H1[(size_t)d0 * D1 + t * 4];
        float w0 = __expf(-leakyv(ss + sd0));
        acc0.x = fmaf(w0, h0.x, acc0.x); acc0.y = fmaf(w0, h0.y, acc0.y);
        acc0.z = fmaf(w0, h0.z, acc0.z); acc0.w = fmaf(w0, h0.w, acc0.w);
        rs0 += w0;
    }
    float inv = 1.f / (rs0 + rs1);
    float o[4] = { eluv((acc0.x + acc1.x) * inv), eluv((acc0.y + acc1.y) * inv),
                   eluv((acc0.z + acc1.z) * inv), eluv((acc0.w + acc1.w) * inv) };
    size_t base = (size_t)n * D1 + t * 4;
    __nv_bfloat16 hh[4], ll[4];
#pragma unroll
    for (int j = 0; j < 4; j++) {
        hh[j] = __float2bfloat16(o[j]);
        ll[j] = __float2bfloat16(o[j] - __bfloat162float(hh[j]));
    }
    __nv_bfloat162* ph = (__nv_bfloat162*)&g_xch[base];
    __nv_bfloat162* pl = (__nv_bfloat162*)&g_xcl[base];
    ph[0] = __halves2bfloat162(hh[0], hh[1]); ph[1] = __halves2bfloat162(hh[2], hh[3]);
    pl[0] = __halves2bfloat162(ll[0], ll[1]); pl[1] = __halves2bfloat162(ll[2], ll[3]);
}

// ---------------- layer-2 aggregation (2 nodes / 128-thr block) ------------
__global__ __launch_bounds__(128) void k_agg2() {
    int n = blockIdx.x * 2 + (threadIdx.x >> 6);
    if (n >= N_NODES) return;
    int t = threadIdx.x & 63;
    float ss = g_S2s[n];
    float acc0 = 0.f, acc1 = 0.f, rs0 = 0.f, rs1 = 0.f;
    int beg = g_rowptr[n], end = g_rowptr[n + 1];
    int e = beg;
    for (; e + 1 < end; e += 2) {
        int d0 = g_dsts[e], d1 = g_dsts[e + 1];
        float sd0 = g_S2d[d0], sd1 = g_S2d[d1];
        float v0 = g_H2[(size_t)d0 * FH + t];
        float v1 = g_H2[(size_t)d1 * FH + t];
        float w0 = __expf(-leakyv(ss + sd0));
        float w1 = __expf(-leakyv(ss + sd1));
        acc0 = fmaf(w0, v0, acc0); rs0 += w0;
        acc1 = fmaf(w1, v1, acc1); rs1 += w1;
    }
    if (e < end) {
        int d0 = g_dsts[e];
        float w0 = __expf(-leakyv(ss + g_S2d[d0]));
        acc0 = fmaf(w0, g_H2[(size_t)d0 * FH + t], acc0); rs0 += w0;
    }
    g_XO[(size_t)n * FH + t] = eluv((acc0 + acc1) / (rs0 + rs1));
}

// ---------------- final classifier ----------------
__global__ __launch_bounds__(256) void k_final(const float* __restrict__ mw,
                                               const float* __restrict__ mb,
                                               float* __restrict__ out) {
    int idx = blockIdx.x * blockDim.x + threadIdx.x;
    if (idx >= N_NODES * NCLASSF) return;
    int n = idx / NCLASSF, c = idx - n * NCLASSF;
    const float4* xo = (const float4*)&g_XO[(size_t)n * FH];
    const float4* wv = (const float4*)&mw[c * FH];
    float s = mb[c];
#pragma unroll
    for (int k = 0; k < FH / 4; k++) {
        float4 a = xo[k], b = wv[k];
        s = fmaf(a.x, b.x, s); s = fmaf(a.y, b.y, s);
        s = fmaf(a.z, b.z, s); s = fmaf(a.w, b.w, s);
    }
    out[idx] = s;
}

// ---------------- launch ----------------
extern "C" void kernel_launch(void* const* d_in, const int* in_sizes, int n_in,
                              void* d_out, int out_size) {
    const float* x  = (const float*)d_in[0];
    const int*   ei = (const int*)d_in[1];
    const float* W  = (const float*)d_in[2];
    const float* a  = (const float*)d_in[3];
    const float* Wo = (const float*)d_in[4];
    const float* ao = (const float*)d_in[5];
    const float* mw = (const float*)d_in[6];
    const float* mb = (const float*)d_in[7];
    float* out = (float*)d_out;

    const int* src = ei;
    const int* dst = ei + N_EDGES;

    float *pH1, *pH2, *pS1s, *pS1d, *pS2s, *pS2d;
    __nv_bfloat16 *pxh, *pxl, *pwth, *pwtl, *pwoth, *pwotl, *pxch, *pxcl;
    cudaGetSymbolAddress((void**)&pH1, g_H1);
    cudaGetSymbolAddress((void**)&pH2, g_H2);
    cudaGetSymbolAddress((void**)&pS1s, g_S1s);
    cudaGetSymbolAddress((void**)&pS1d, g_S1d);
    cudaGetSymbolAddress((void**)&pS2s, g_S2s);
    cudaGetSymbolAddress((void**)&pS2d, g_S2d);
    cudaGetSymbolAddress((void**)&pxh, g_xh);
    cudaGetSymbolAddress((void**)&pxl, g_xl);
    cudaGetSymbolAddress((void**)&pwth, g_wth);
    cudaGetSymbolAddress((void**)&pwtl, g_wtl);
    cudaGetSymbolAddress((void**)&pwoth, g_woth);
    cudaGetSymbolAddress((void**)&pwotl, g_wotl);
    cudaGetSymbolAddress((void**)&pxch, g_xch);
    cudaGetSymbolAddress((void**)&pxcl, g_xcl);

    // CSR build
    k_zero_cnt<<<(N_NODES + 255) / 256, 256>>>();
    k_hist<<<(N_EDGES + 255) / 256, 256>>>(src);
    k_scan<<<1, 1024>>>();
    k_scatter<<<(N_EDGES + 255) / 256, 256>>>(src, dst);

    // operand splits
    k_split_x<<<(N_NODES * F_INF / 4 + 255) / 256, 256>>>(x, pxh, pxl, N_NODES * F_INF / 4);
    k_split_wt<<<(NHEADS * F_INF * FH + 255) / 256, 256>>>(W, pwth, pwtl);
    k_split_wot<<<(D1 * FH + 255) / 256, 256>>>(Wo, pwoth, pwotl);

    // layer 1: H1 = x @ W per head (mma.sync bf16x3, ldmatrix+prefetch) + fused scores
    dim3 g1((N_NODES + BM - 1) / BM, NHEADS);
    k_gemm_mma<<<g1, 256>>>(pxh, pxl, pwth, pwtl, N_NODES, F_INF,
                            pH1, D1, a, pS1s, pS1d, NHEADS);
    k_agg1<<<N_NODES, 128>>>();

    // layer 2: H2 = XC @ Wo + fused scores
    dim3 g2((N_NODES + BM - 1) / BM, 1);
    k_gemm_mma<<<g2, 256>>>(pxch, pxcl, pwoth, pwotl, N_NODES, D1,
                            pH2, FH, ao, pS2s, pS2d, 1);
    k_agg2<<<(N_NODES + 1) / 2, 128>>>();

    // classifier
    k_final<<<(N_NODES * NCLASSF + 255) / 256, 256>>>(mw, mb, out);
}

// round 6
// speedup vs baseline: 2.2572x; 1.1729x over previous
#include <cuda_runtime.h>
#include <cuda_bf16.h>
#include <cstdint>

#define N_NODES 50000
#define N_EDGES 850000
#define F_INF   256
#define FH      64
#define NHEADS  8
#define NCLASSF 40
#define ALPHAF  0.2f
#define D1      (NHEADS * FH)   // 512

// ---------------- device scratch ----------------
__device__ float g_H1[(size_t)N_NODES * D1];
__device__ float g_S1s[N_NODES * NHEADS];
__device__ float g_S1d[N_NODES * NHEADS];
__device__ float g_H2[(size_t)N_NODES * FH];
__device__ float g_XO[(size_t)N_NODES * FH];
__device__ float g_S2s[N_NODES];
__device__ float g_S2d[N_NODES];
__device__ int   g_rowptr[N_NODES + 1];
__device__ int   g_cnt[N_NODES];
__device__ int   g_pos[N_NODES];
__device__ int   g_dsts[N_EDGES];
// bf16 split operands
__device__ __nv_bfloat16 g_xh[(size_t)N_NODES * F_INF];
__device__ __nv_bfloat16 g_xl[(size_t)N_NODES * F_INF];
__device__ __nv_bfloat16 g_wth[NHEADS * FH * F_INF];
__device__ __nv_bfloat16 g_wtl[NHEADS * FH * F_INF];
__device__ __nv_bfloat16 g_woth[FH * D1];
__device__ __nv_bfloat16 g_wotl[FH * D1];
__device__ __nv_bfloat16 g_xch[(size_t)N_NODES * D1];
__device__ __nv_bfloat16 g_xcl[(size_t)N_NODES * D1];

__device__ __forceinline__ float leakyv(float v) { return v > 0.f ? v : ALPHAF * v; }
__device__ __forceinline__ float eluv(float v)   { return v > 0.f ? v : expm1f(v); }

// ---------------- CSR build ----------------
__global__ void k_zero_cnt() {
    int i = blockIdx.x * blockDim.x + threadIdx.x;
    if (i < N_NODES) g_cnt[i] = 0;
}
__global__ void k_hist(const int* __restrict__ src) {
    int e = blockIdx.x * blockDim.x + threadIdx.x;
    if (e < N_EDGES) atomicAdd(&g_cnt[src[e]], 1);
}
__global__ __launch_bounds__(1024) void k_scan() {
    __shared__ int s[1024];
    const int CH = 49;
    int t = threadIdx.x;
    int start = t * CH;
    int end = start + CH; if (end > N_NODES) end = N_NODES;
    int sum = 0;
    for (int i = start; i < end; i++) sum += g_cnt[i];
    s[t] = sum;
    __syncthreads();
    for (int off = 1; off < 1024; off <<= 1) {
        int v = (t >= off) ? s[t - off] : 0;
        __syncthreads();
        s[t] += v;
        __syncthreads();
    }
    int run = (t == 0) ? 0 : s[t - 1];
    for (int i = start; i < end; i++) {
        g_rowptr[i] = run;
        g_pos[i] = run;
        run += g_cnt[i];
    }
    if (t == 0) g_rowptr[N_NODES] = s[1023];
}
__global__ void k_scatter(const int* __restrict__ src, const int* __restrict__ dst) {
    int e = blockIdx.x * blockDim.x + threadIdx.x;
    if (e < N_EDGES) {
        int p = atomicAdd(&g_pos[src[e]], 1);
        g_dsts[p] = dst[e];
    }
}

// ---------------- bf16 hi/lo splits ----------------
__global__ void k_split_x(const float* __restrict__ x, __nv_bfloat16* __restrict__ oh,
                          __nv_bfloat16* __restrict__ ol, int n4) {
    int i = blockIdx.x * blockDim.x + threadIdx.x;
    if (i >= n4) return;
    float4 v = ((const float4*)x)[i];
    __nv_bfloat16 h0 = __float2bfloat16(v.x), h1 = __float2bfloat16(v.y);
    __nv_bfloat16 h2 = __float2bfloat16(v.z), h3 = __float2bfloat16(v.w);
    __nv_bfloat16 l0 = __float2bfloat16(v.x - __bfloat162float(h0));
    __nv_bfloat16 l1 = __float2bfloat16(v.y - __bfloat162float(h1));
    __nv_bfloat16 l2 = __float2bfloat16(v.z - __bfloat162float(h2));
    __nv_bfloat16 l3 = __float2bfloat16(v.w - __bfloat162float(h3));
    __nv_bfloat162* ph = (__nv_bfloat162*)(oh) + i * 2;
    __nv_bfloat162* pl = (__nv_bfloat162*)(ol) + i * 2;
    ph[0] = __halves2bfloat162(h0, h1); ph[1] = __halves2bfloat162(h2, h3);
    pl[0] = __halves2bfloat162(l0, l1); pl[1] = __halves2bfloat162(l2, l3);
}
// W[h][k][n] (fp32) -> out[h][n][k] bf16 hi/lo
__global__ void k_split_wt(const float* __restrict__ W, __nv_bfloat16* __restrict__ oh,
                           __nv_bfloat16* __restrict__ ol) {
    int i = blockIdx.x * blockDim.x + threadIdx.x;
    if (i >= NHEADS * F_INF * FH) return;
    int h = i / (F_INF * FH), r = i % (F_INF * FH), k = r / FH, n = r % FH;
    float v = W[i];
    __nv_bfloat16 hh = __float2bfloat16(v);
    __nv_bfloat16 ll = __float2bfloat16(v - __bfloat162float(hh));
    size_t o = (size_t)(h * FH + n) * F_INF + k;
    oh[o] = hh; ol[o] = ll;
}
// Wo[k][n] -> out[n][k]
__global__ void k_split_wot(const float* __restrict__ Wo, __nv_bfloat16* __restrict__ oh,
                            __nv_bfloat16* __restrict__ ol) {
    int i = blockIdx.x * blockDim.x + threadIdx.x;
    if (i >= D1 * FH) return;
    int k = i / FH, n = i % FH;
    float v = Wo[i];
    __nv_bfloat16 hh = __float2bfloat16(v);
    __nv_bfloat16 ll = __float2bfloat16(v - __bfloat162float(hh));
    size_t o = (size_t)n * D1 + k;
    oh[o] = hh; ol[o] = ll;
}

// ---------------- mma.sync bf16x3 GEMM, cp.async double-buffered ----------
#define BM 128
#define BN 64
#define BK 32
#define AST 40                      // padded row stride in bf16 (80B)
#define STG 30720                   // bytes per pipeline stage
#define OFF_AH 0
#define OFF_AL 10240
#define OFF_BH 20480
#define OFF_BL 25600
#define GSMEM  (2 * STG + 2048)     // + red[2][128][2] floats

__device__ __forceinline__ void mma16816(float* d, const uint32_t* a, const uint32_t* b) {
    asm volatile(
        "mma.sync.aligned.m16n8k16.row.col.f32.bf16.bf16.f32 "
        "{%0,%1,%2,%3},{%4,%5,%6,%7},{%8,%9},{%0,%1,%2,%3};"
        : "+f"(d[0]), "+f"(d[1]), "+f"(d[2]), "+f"(d[3])
        : "r"(a[0]), "r"(a[1]), "r"(a[2]), "r"(a[3]), "r"(b[0]), "r"(b[1]));
}
__device__ __forceinline__ void ldsm4(uint32_t* r, const void* p) {
    uint32_t addr = (uint32_t)__cvta_generic_to_shared(p);
    asm volatile("ldmatrix.sync.aligned.m8n8.x4.shared.b16 {%0,%1,%2,%3}, [%4];"
                 : "=r"(r[0]), "=r"(r[1]), "=r"(r[2]), "=r"(r[3]) : "r"(addr));
}
__device__ __forceinline__ void cp_async16(uint32_t saddr, const void* g, int sz) {
    asm volatile("cp.async.cg.shared.global [%0], [%1], 16, %2;"
                 :: "r"(saddr), "l"(g), "r"(sz));
}
#define CP_COMMIT() asm volatile("cp.async.commit_group;")
#define CP_WAIT0()  asm volatile("cp.async.wait_group 0;")

__global__ __launch_bounds__(256) void k_gemm_mma(
    const __nv_bfloat16* __restrict__ Ah, const __nv_bfloat16* __restrict__ Al,
    const __nv_bfloat16* __restrict__ Bh, const __nv_bfloat16* __restrict__ Bl,
    int M, int K, float* __restrict__ C, int ldc,
    const float* __restrict__ att, float* __restrict__ Ss, float* __restrict__ Sd,
    int sstride)
{
    extern __shared__ char sm[];
    uint32_t sbase = (uint32_t)__cvta_generic_to_shared(sm);
    float* redp = (float*)(sm + 2 * STG);   // [2][BM][2]

    int tid = threadIdx.x, lane = tid & 31, wid = tid >> 5;
    int wm = wid & 3, wn = wid >> 2;        // warp grid 4(m) x 2(n)
    int m0 = blockIdx.x * BM;
    int bidy = blockIdx.y;
    Bh += (size_t)bidy * FH * K;
    Bl += (size_t)bidy * FH * K;
    att += bidy * 2 * FH;
    int coloff = bidy * FH;

    float acc[2][4][4];
#pragma unroll
    for (int i = 0; i < 2; i++)
#pragma unroll
        for (int j = 0; j < 4; j++)
#pragma unroll
            for (int l = 0; l < 4; l++) acc[i][j][l] = 0.f;

    int q = lane >> 2, cq = (lane & 3) * 2;

    // per-thread staging map: 6 chunks of 16B; sel: 0 Ah,1 Al,2 Bh,3 Bl
    int st_row[6], st_q[6], st_sel[6];
#pragma unroll
    for (int l = 0; l < 6; l++) {
        int it = tid + l * 256;
        if (it < 1024) {
            int p = it >> 9, i = it & 511;
            st_sel[l] = p; st_row[l] = i >> 2; st_q[l] = i & 3;
        } else {
            int j = it - 1024, p = j >> 8, i = j & 255;
            st_sel[l] = 2 + p; st_row[l] = i >> 2; st_q[l] = i & 3;
        }
    }
    const int seloff[4] = {OFF_AH, OFF_AL, OFF_BH, OFF_BL};

    auto issue_tile = [&](int k0, int bo) {
#pragma unroll
        for (int l = 0; l < 6; l++) {
            int row = st_row[l], qq = st_q[l], sel = st_sel[l];
            const __nv_bfloat16* g;
            int sz = 16;
            if (sel < 2) {
                int m = m0 + row;
                if (m >= M) { sz = 0; m = 0; }
                g = (sel ? Al : Ah) + (size_t)m * K + k0 + qq * 8;
            } else {
                g = (sel == 2 ? Bh : Bl) + (size_t)row * K + k0 + qq * 8;
            }
            cp_async16(sbase + bo + seloff[sel] + row * 80 + qq * 16, g, sz);
        }
    };

    issue_tile(0, 0);
    CP_COMMIT();

    int arow = lane & 15, ak = (lane >> 4) * 8;
    int brow = (lane & 7) + ((lane >> 4) << 3), bk = ((lane >> 3) & 1) * 8;
    int bo = 0;

    for (int k0 = 0; k0 < K; k0 += BK) {
        CP_WAIT0();
        __syncthreads();
        if (k0 + BK < K) {
            issue_tile(k0 + BK, bo ^ STG);
            CP_COMMIT();
        }
        const __nv_bfloat16* sAh = (const __nv_bfloat16*)(sm + bo + OFF_AH);
        const __nv_bfloat16* sAl = (const __nv_bfloat16*)(sm + bo + OFF_AL);
        const __nv_bfloat16* sBh = (const __nv_bfloat16*)(sm + bo + OFF_BH);
        const __nv_bfloat16* sBl = (const __nv_bfloat16*)(sm + bo + OFF_BL);

#pragma unroll
        for (int kf = 0; kf < 2; kf++) {
            int c0 = kf * 16;
            uint32_t ah[2][4], al[2][4], bhf[4][2], blf[4][2];
#pragma unroll
            for (int mf = 0; mf < 2; mf++) {
                int r = (wm * 32 + mf * 16 + arow) * AST + c0 + ak;
                ldsm4(ah[mf], &sAh[r]);
                ldsm4(al[mf], &sAl[r]);
            }
#pragma unroll
            for (int nfp = 0; nfp < 2; nfp++) {
                int r = (wn * 32 + nfp * 16 + brow) * AST + c0 + bk;
                uint32_t tb[4], tl[4];
                ldsm4(tb, &sBh[r]);
                ldsm4(tl, &sBl[r]);
                bhf[2 * nfp][0] = tb[0]; bhf[2 * nfp][1] = tb[1];
                bhf[2 * nfp + 1][0] = tb[2]; bhf[2 * nfp + 1][1] = tb[3];
                blf[2 * nfp][0] = tl[0]; blf[2 * nfp][1] = tl[1];
                blf[2 * nfp + 1][0] = tl[2]; blf[2 * nfp + 1][1] = tl[3];
            }
#pragma unroll
            for (int mf = 0; mf < 2; mf++)
#pragma unroll
                for (int nf = 0; nf < 4; nf++) {
                    mma16816(acc[mf][nf], ah[mf], bhf[nf]);
                    mma16816(acc[mf][nf], ah[mf], blf[nf]);
                    mma16816(acc[mf][nf], al[mf], bhf[nf]);
                }
        }
        bo ^= STG;
    }

    // ---- epilogue: store C, fused score dot products ----
    float sp[2][2][2];
#pragma unroll
    for (int mf = 0; mf < 2; mf++)
#pragma unroll
        for (int h = 0; h < 2; h++) { sp[mf][h][0] = 0.f; sp[mf][h][1] = 0.f; }

#pragma unroll
    for (int mf = 0; mf < 2; mf++) {
        int r = wm * 32 + mf * 16 + q;
        int mr = m0 + r;
#pragma unroll
        for (int nf = 0; nf < 4; nf++) {
            int c = wn * 32 + nf * 8 + cq;
            float d0 = acc[mf][nf][0], d1 = acc[mf][nf][1];
            float d2 = acc[mf][nf][2], d3 = acc[mf][nf][3];
            if (mr < M) *(float2*)&C[(size_t)mr * ldc + coloff + c] = make_float2(d0, d1);
            if (mr + 8 < M) *(float2*)&C[(size_t)(mr + 8) * ldc + coloff + c] = make_float2(d2, d3);
            float a0 = att[c], a1 = att[c + 1], a2 = att[FH + c], a3 = att[FH + c + 1];
            sp[mf][0][0] = fmaf(d0, a0, fmaf(d1, a1, sp[mf][0][0]));
            sp[mf][0][1] = fmaf(d0, a2, fmaf(d1, a3, sp[mf][0][1]));
            sp[mf][1][0] = fmaf(d2, a0, fmaf(d3, a1, sp[mf][1][0]));
            sp[mf][1][1] = fmaf(d2, a2, fmaf(d3, a3, sp[mf][1][1]));
        }
    }
#pragma unroll
    for (int mf = 0; mf < 2; mf++)
#pragma unroll
        for (int h = 0; h < 2; h++)
#pragma unroll
            for (int sc = 0; sc < 2; sc++) {
                float v = sp[mf][h][sc];
                v += __shfl_xor_sync(0xffffffffu, v, 1);
                v += __shfl_xor_sync(0xffffffffu, v, 2);
                sp[mf][h][sc] = v;
            }
    if ((lane & 3) == 0) {
#pragma unroll
        for (int mf = 0; mf < 2; mf++)
#pragma unroll
            for (int h = 0; h < 2; h++) {
                int r = wm * 32 + mf * 16 + q + h * 8;
                redp[(wn * BM + r) * 2 + 0] = sp[mf][h][0];
                redp[(wn * BM + r) * 2 + 1] = sp[mf][h][1];
            }
    }
    __syncthreads();
    if (tid < BM) {
        int m = m0 + tid;
        if (m < M) {
            Ss[(size_t)m * sstride + bidy] = redp[tid * 2] + redp[(BM + tid) * 2];
            Sd[(size_t)m * sstride + bidy] = redp[tid * 2 + 1] + redp[(BM + tid) * 2 + 1];
        }
    }
}

// ---------------- layer-1 aggregation (8 heads fused) -> bf16 split XC -----
__global__ __launch_bounds__(128) void k_agg1() {
    int n = blockIdx.x, t = threadIdx.x;
    int head = t >> 4;
    float ss = g_S1s[n * NHEADS + head];
    float4 acc0 = make_float4(0.f, 0.f, 0.f, 0.f);
    float4 acc1 = make_float4(0.f, 0.f, 0.f, 0.f);
    float rs0 = 0.f, rs1 = 0.f;
    int beg = g_rowptr[n], end = g_rowptr[n + 1];
    int e = beg;
    for (; e + 1 < end; e += 2) {
        int d0 = g_dsts[e], d1 = g_dsts[e + 1];
        float sd0 = g_S1d[d0 * NHEADS + head];
        float sd1 = g_S1d[d1 * NHEADS + head];
        float4 h0 = *(const float4*)&g_H1[(size_t)d0 * D1 + t * 4];
        float4 h1 = *(const float4*)&g_H1[(size_t)d1 * D1 + t * 4];
        float w0 = __expf(-leakyv(ss + sd0));
        float w1 = __expf(-leakyv(ss + sd1));
        acc0.x = fmaf(w0, h0.x, acc0.x); acc0.y = fmaf(w0, h0.y, acc0.y);
        acc0.z = fmaf(w0, h0.z, acc0.z); acc0.w = fmaf(w0, h0.w, acc0.w);
        acc1.x = fmaf(w1, h1.x, acc1.x); acc1.y = fmaf(w1, h1.y, acc1.y);
        acc1.z = fmaf(w1, h1.z, acc1.z); acc1.w = fmaf(w1, h1.w, acc1.w);
        rs0 += w0; rs1 += w1;
    }
    if (e < end) {
        int d0 = g_dsts[e];
        float sd0 = g_S1d[d0 * NHEADS + head];
        float4 h0 = *(const float4*)&g_H1[(size_t)d0 * D1 + t * 4];
        float w0 = __expf(-leakyv(ss + sd0));
        acc0.x = fmaf(w0, h0.x, acc0.x); acc0.y = fmaf(w0, h0.y, acc0.y);
        acc0.z = fmaf(w0, h0.z, acc0.z); acc0.w = fmaf(w0, h0.w, acc0.w);
        rs0 += w0;
    }
    float inv = 1.f / (rs0 + rs1);
    float o[4] = { eluv((acc0.x + acc1.x) * inv), eluv((acc0.y + acc1.y) * inv),
                   eluv((acc0.z + acc1.z) * inv), eluv((acc0.w + acc1.w) * inv) };
    size_t base = (size_t)n * D1 + t * 4;
    __nv_bfloat16 hh[4], ll[4];
#pragma unroll
    for (int j = 0; j < 4; j++) {
        hh[j] = __float2bfloat16(o[j]);
        ll[j] = __float2bfloat16(o[j] - __bfloat162float(hh[j]));
    }
    __nv_bfloat162* ph = (__nv_bfloat162*)&g_xch[base];
    __nv_bfloat162* pl = (__nv_bfloat162*)&g_xcl[base];
    ph[0] = __halves2bfloat162(hh[0], hh[1]); ph[1] = __halves2bfloat162(hh[2], hh[3]);
    pl[0] = __halves2bfloat162(ll[0], ll[1]); pl[1] = __halves2bfloat162(ll[2], ll[3]);
}

// ---------------- layer-2 aggregation (2 nodes / 128-thr block) ------------
__global__ __launch_bounds__(128) void k_agg2() {
    int n = blockIdx.x * 2 + (threadIdx.x >> 6);
    if (n >= N_NODES) return;
    int t = threadIdx.x & 63;
    float ss = g_S2s[n];
    float acc0 = 0.f, acc1 = 0.f, rs0 = 0.f, rs1 = 0.f;
    int beg = g_rowptr[n], end = g_rowptr[n + 1];
    int e = beg;
    for (; e + 1 < end; e += 2) {
        int d0 = g_dsts[e], d1 = g_dsts[e + 1];
        float sd0 = g_S2d[d0], sd1 = g_S2d[d1];
        float v0 = g_H2[(size_t)d0 * FH + t];
        float v1 = g_H2[(size_t)d1 * FH + t];
        float w0 = __expf(-leakyv(ss + sd0));
        float w1 = __expf(-leakyv(ss + sd1));
        acc0 = fmaf(w0, v0, acc0); rs0 += w0;
        acc1 = fmaf(w1, v1, acc1); rs1 += w1;
    }
    if (e < end) {
        int d0 = g_dsts[e];
        float w0 = __expf(-leakyv(ss + g_S2d[d0]));
        acc0 = fmaf(w0, g_H2[(size_t)d0 * FH + t], acc0); rs0 += w0;
    }
    g_XO[(size_t)n * FH + t] = eluv((acc0 + acc1) / (rs0 + rs1));
}

// ---------------- final classifier ----------------
__global__ __launch_bounds__(256) void k_final(const float* __restrict__ mw,
                                               const float* __restrict__ mb,
                                               float* __restrict__ out) {
    int idx = blockIdx.x * blockDim.x + threadIdx.x;
    if (idx >= N_NODES * NCLASSF) return;
    int n = idx / NCLASSF, c = idx - n * NCLASSF;
    const float4* xo = (const float4*)&g_XO[(size_t)n * FH];
    const float4* wv = (const float4*)&mw[c * FH];
    float s = mb[c];
#pragma unroll
    for (int k = 0; k < FH / 4; k++) {
        float4 a = xo[k], b = wv[k];
        s = fmaf(a.x, b.x, s); s = fmaf(a.y, b.y, s);
        s = fmaf(a.z, b.z, s); s = fmaf(a.w, b.w, s);
    }
    out[idx] = s;
}

// ---------------- launch (fork-join multi-stream capture) -------------------
extern "C" void kernel_launch(void* const* d_in, const int* in_sizes, int n_in,
                              void* d_out, int out_size) {
    const float* x  = (const float*)d_in[0];
    const int*   ei = (const int*)d_in[1];
    const float* W  = (const float*)d_in[2];
    const float* a  = (const float*)d_in[3];
    const float* Wo = (const float*)d_in[4];
    const float* ao = (const float*)d_in[5];
    const float* mw = (const float*)d_in[6];
    const float* mb = (const float*)d_in[7];
    float* out = (float*)d_out;

    const int* src = ei;
    const int* dst = ei + N_EDGES;

    float *pH1, *pH2, *pS1s, *pS1d, *pS2s, *pS2d;
    __nv_bfloat16 *pxh, *pxl, *pwth, *pwtl, *pwoth, *pwotl, *pxch, *pxcl;
    cudaGetSymbolAddress((void**)&pH1, g_H1);
    cudaGetSymbolAddress((void**)&pH2, g_H2);
    cudaGetSymbolAddress((void**)&pS1s, g_S1s);
    cudaGetSymbolAddress((void**)&pS1d, g_S1d);
    cudaGetSymbolAddress((void**)&pS2s, g_S2s);
    cudaGetSymbolAddress((void**)&pS2d, g_S2d);
    cudaGetSymbolAddress((void**)&pxh, g_xh);
    cudaGetSymbolAddress((void**)&pxl, g_xl);
    cudaGetSymbolAddress((void**)&pwth, g_wth);
    cudaGetSymbolAddress((void**)&pwtl, g_wtl);
    cudaGetSymbolAddress((void**)&pwoth, g_woth);
    cudaGetSymbolAddress((void**)&pwotl, g_wotl);
    cudaGetSymbolAddress((void**)&pxch, g_xch);
    cudaGetSymbolAddress((void**)&pxcl, g_xcl);

    cudaFuncSetAttribute(k_gemm_mma, cudaFuncAttributeMaxDynamicSharedMemorySize, GSMEM);

    cudaStream_t s2;
    cudaStreamCreate(&s2);
    cudaEvent_t evF, evJ;
    cudaEventCreateWithFlags(&evF, cudaEventDisableTiming);
    cudaEventCreateWithFlags(&evJ, cudaEventDisableTiming);

    // fork: side stream runs the CSR chain + Wo split
    cudaEventRecord(evF, 0);
    cudaStreamWaitEvent(s2, evF, 0);
    k_zero_cnt<<<(N_NODES + 255) / 256, 256, 0, s2>>>();
    k_hist<<<(N_EDGES + 255) / 256, 256, 0, s2>>>(src);
    k_scan<<<1, 1024, 0, s2>>>();
    k_scatter<<<(N_EDGES + 255) / 256, 256, 0, s2>>>(src, dst);
    k_split_wot<<<(D1 * FH + 255) / 256, 256, 0, s2>>>(Wo, pwoth, pwotl);
    cudaEventRecord(evJ, s2);

    // main stream: splits + GEMM1 (overlaps CSR chain)
    k_split_x<<<(N_NODES * F_INF / 4 + 255) / 256, 256>>>(x, pxh, pxl, N_NODES * F_INF / 4);
    k_split_wt<<<(NHEADS * F_INF * FH + 255) / 256, 256>>>(W, pwth, pwtl);
    dim3 g1((N_NODES + BM - 1) / BM, NHEADS);
    k_gemm_mma<<<g1, 256, GSMEM>>>(pxh, pxl, pwth, pwtl, N_NODES, F_INF,
                                   pH1, D1, a, pS1s, pS1d, NHEADS);

    // join: aggregation needs CSR + GEMM1
    cudaStreamWaitEvent(0, evJ, 0);
    k_agg1<<<N_NODES, 128>>>();

    dim3 g2((N_NODES + BM - 1) / BM, 1);
    k_gemm_mma<<<g2, 256, GSMEM>>>(pxch, pxcl, pwoth, pwotl, N_NODES, D1,
                                   pH2, FH, ao, pS2s, pS2d, 1);
    k_agg2<<<(N_NODES + 1) / 2, 128>>>();

    k_final<<<(N_NODES * NCLASSF + 255) / 256, 256>>>(mw, mb, out);

    cudaEventDestroy(evF);
    cudaEventDestroy(evJ);
    cudaStreamDestroy(s2);
}

// round 7
// speedup vs baseline: 2.3234x; 1.0293x over previous
#include <cuda_runtime.h>
#include <cuda_bf16.h>
#include <cstdint>

#define N_NODES 50000
#define N_EDGES 850000
#define F_INF   256
#define FH      64
#define NHEADS  8
#define NCLASSF 40
#define ALPHAF  0.2f
#define D1      (NHEADS * FH)   // 512

// ---------------- device scratch ----------------
__device__ float g_H1[(size_t)N_NODES * D1];
__device__ float g_S1s[N_NODES * NHEADS];
__device__ float g_S1d[N_NODES * NHEADS];
__device__ float g_H2[(size_t)N_NODES * FH];
__device__ float g_S2s[N_NODES];
__device__ float g_S2d[N_NODES];
__device__ int   g_rowptr[N_NODES + 1];
__device__ int   g_cnt[N_NODES];
__device__ int   g_pos[N_NODES];
__device__ int   g_dsts[N_EDGES];
// bf16 split operands
__device__ __nv_bfloat16 g_xh[(size_t)N_NODES * F_INF];
__device__ __nv_bfloat16 g_xl[(size_t)N_NODES * F_INF];
__device__ __nv_bfloat16 g_wth[NHEADS * FH * F_INF];
__device__ __nv_bfloat16 g_wtl[NHEADS * FH * F_INF];
__device__ __nv_bfloat16 g_woth[FH * D1];
__device__ __nv_bfloat16 g_wotl[FH * D1];
__device__ __nv_bfloat16 g_xch[(size_t)N_NODES * D1];
__device__ __nv_bfloat16 g_xcl[(size_t)N_NODES * D1];

__device__ __forceinline__ float leakyv(float v) { return v > 0.f ? v : ALPHAF * v; }
__device__ __forceinline__ float eluv(float v)   { return v > 0.f ? v : expm1f(v); }

// ---------------- CSR build ----------------
__global__ void k_zero_cnt() {
    int i = blockIdx.x * blockDim.x + threadIdx.x;
    if (i < N_NODES) g_cnt[i] = 0;
}
__global__ void k_hist(const int* __restrict__ src) {
    int e = blockIdx.x * blockDim.x + threadIdx.x;
    if (e < N_EDGES) atomicAdd(&g_cnt[src[e]], 1);
}
__global__ __launch_bounds__(1024) void k_scan() {
    __shared__ int s[1024];
    const int CH = 49;
    int t = threadIdx.x;
    int start = t * CH;
    int end = start + CH; if (end > N_NODES) end = N_NODES;
    int sum = 0;
    for (int i = start; i < end; i++) sum += g_cnt[i];
    s[t] = sum;
    __syncthreads();
    for (int off = 1; off < 1024; off <<= 1) {
        int v = (t >= off) ? s[t - off] : 0;
        __syncthreads();
        s[t] += v;
        __syncthreads();
    }
    int run = (t == 0) ? 0 : s[t - 1];
    for (int i = start; i < end; i++) {
        g_rowptr[i] = run;
        g_pos[i] = run;
        run += g_cnt[i];
    }
    if (t == 0) g_rowptr[N_NODES] = s[1023];
}
__global__ void k_scatter(const int* __restrict__ src, const int* __restrict__ dst) {
    int e = blockIdx.x * blockDim.x + threadIdx.x;
    if (e < N_EDGES) {
        int p = atomicAdd(&g_pos[src[e]], 1);
        g_dsts[p] = dst[e];
    }
}

// ---------------- bf16 hi/lo splits ----------------
__global__ void k_split_x(const float* __restrict__ x, __nv_bfloat16* __restrict__ oh,
                          __nv_bfloat16* __restrict__ ol, int n4) {
    int i = blockIdx.x * blockDim.x + threadIdx.x;
    if (i >= n4) return;
    float4 v = ((const float4*)x)[i];
    __nv_bfloat16 h0 = __float2bfloat16(v.x), h1 = __float2bfloat16(v.y);
    __nv_bfloat16 h2 = __float2bfloat16(v.z), h3 = __float2bfloat16(v.w);
    __nv_bfloat16 l0 = __float2bfloat16(v.x - __bfloat162float(h0));
    __nv_bfloat16 l1 = __float2bfloat16(v.y - __bfloat162float(h1));
    __nv_bfloat16 l2 = __float2bfloat16(v.z - __bfloat162float(h2));
    __nv_bfloat16 l3 = __float2bfloat16(v.w - __bfloat162float(h3));
    __nv_bfloat162* ph = (__nv_bfloat162*)(oh) + i * 2;
    __nv_bfloat162* pl = (__nv_bfloat162*)(ol) + i * 2;
    ph[0] = __halves2bfloat162(h0, h1); ph[1] = __halves2bfloat162(h2, h3);
    pl[0] = __halves2bfloat162(l0, l1); pl[1] = __halves2bfloat162(l2, l3);
}
// W[h][k][n] (fp32) -> out[h][n][k] bf16 hi/lo
__global__ void k_split_wt(const float* __restrict__ W, __nv_bfloat16* __restrict__ oh,
                           __nv_bfloat16* __restrict__ ol) {
    int i = blockIdx.x * blockDim.x + threadIdx.x;
    if (i >= NHEADS * F_INF * FH) return;
    int h = i / (F_INF * FH), r = i % (F_INF * FH), k = r / FH, n = r % FH;
    float v = W[i];
    __nv_bfloat16 hh = __float2bfloat16(v);
    __nv_bfloat16 ll = __float2bfloat16(v - __bfloat162float(hh));
    size_t o = (size_t)(h * FH + n) * F_INF + k;
    oh[o] = hh; ol[o] = ll;
}
// Wo[k][n] -> out[n][k]
__global__ void k_split_wot(const float* __restrict__ Wo, __nv_bfloat16* __restrict__ oh,
                            __nv_bfloat16* __restrict__ ol) {
    int i = blockIdx.x * blockDim.x + threadIdx.x;
    if (i >= D1 * FH) return;
    int k = i / FH, n = i % FH;
    float v = Wo[i];
    __nv_bfloat16 hh = __float2bfloat16(v);
    __nv_bfloat16 ll = __float2bfloat16(v - __bfloat162float(hh));
    size_t o = (size_t)n * D1 + k;
    oh[o] = hh; ol[o] = ll;
}

// ---------------- mma.sync bf16x3 GEMM, 3-stage cp.async pipeline ----------
#define BM 128
#define BN 64
#define BK 32
#define AST 40                      // padded row stride in bf16 (80B)
#define STG 30720                   // bytes per pipeline stage
#define NSTAGE 3
#define OFF_AH 0
#define OFF_AL 10240
#define OFF_BH 20480
#define OFF_BL 25600
#define GSMEM  (NSTAGE * STG + 2048)

__device__ __forceinline__ void mma16816(float* d, const uint32_t* a, const uint32_t* b) {
    asm volatile(
        "mma.sync.aligned.m16n8k16.row.col.f32.bf16.bf16.f32 "
        "{%0,%1,%2,%3},{%4,%5,%6,%7},{%8,%9},{%0,%1,%2,%3};"
        : "+f"(d[0]), "+f"(d[1]), "+f"(d[2]), "+f"(d[3])
        : "r"(a[0]), "r"(a[1]), "r"(a[2]), "r"(a[3]), "r"(b[0]), "r"(b[1]));
}
__device__ __forceinline__ void ldsm4(uint32_t* r, const void* p) {
    uint32_t addr = (uint32_t)__cvta_generic_to_shared(p);
    asm volatile("ldmatrix.sync.aligned.m8n8.x4.shared.b16 {%0,%1,%2,%3}, [%4];"
                 : "=r"(r[0]), "=r"(r[1]), "=r"(r[2]), "=r"(r[3]) : "r"(addr));
}
__device__ __forceinline__ void cp_async16(uint32_t saddr, const void* g, int sz) {
    asm volatile("cp.async.cg.shared.global [%0], [%1], 16, %2;"
                 :: "r"(saddr), "l"(g), "r"(sz));
}
#define CP_COMMIT() asm volatile("cp.async.commit_group;")
#define CP_WAIT0()  asm volatile("cp.async.wait_group 0;")
#define CP_WAIT1()  asm volatile("cp.async.wait_group 1;")

__global__ __launch_bounds__(256) void k_gemm_mma(
    const __nv_bfloat16* __restrict__ Ah, const __nv_bfloat16* __restrict__ Al,
    const __nv_bfloat16* __restrict__ Bh, const __nv_bfloat16* __restrict__ Bl,
    int M, int K, float* __restrict__ C, int ldc,
    const float* __restrict__ att, float* __restrict__ Ss, float* __restrict__ Sd,
    int sstride)
{
    extern __shared__ char sm[];
    uint32_t sbase = (uint32_t)__cvta_generic_to_shared(sm);
    float* redp = (float*)(sm + NSTAGE * STG);   // [2][BM][2]

    int tid = threadIdx.x, lane = tid & 31, wid = tid >> 5;
    int wm = wid & 3, wn = wid >> 2;        // warp grid 4(m) x 2(n)
    int m0 = blockIdx.x * BM;
    int bidy = blockIdx.y;
    Bh += (size_t)bidy * FH * K;
    Bl += (size_t)bidy * FH * K;
    att += bidy * 2 * FH;
    int coloff = bidy * FH;

    float acc[2][4][4];
#pragma unroll
    for (int i = 0; i < 2; i++)
#pragma unroll
        for (int j = 0; j < 4; j++)
#pragma unroll
            for (int l = 0; l < 4; l++) acc[i][j][l] = 0.f;

    int q = lane >> 2, cq = (lane & 3) * 2;

    // per-thread staging map: 6 chunks of 16B; sel: 0 Ah,1 Al,2 Bh,3 Bl
    int st_row[6], st_q[6], st_sel[6];
#pragma unroll
    for (int l = 0; l < 6; l++) {
        int it = tid + l * 256;
        if (it < 1024) {
            int p = it >> 9, i = it & 511;
            st_sel[l] = p; st_row[l] = i >> 2; st_q[l] = i & 3;
        } else {
            int j = it - 1024, p = j >> 8, i = j & 255;
            st_sel[l] = 2 + p; st_row[l] = i >> 2; st_q[l] = i & 3;
        }
    }
    const int seloff[4] = {OFF_AH, OFF_AL, OFF_BH, OFF_BL};

    auto issue_tile = [&](int k0, int slot) {
        uint32_t bo = sbase + slot * STG;
#pragma unroll
        for (int l = 0; l < 6; l++) {
            int row = st_row[l], qq = st_q[l], sel = st_sel[l];
            const __nv_bfloat16* g;
            int sz = 16;
            if (sel < 2) {
                int m = m0 + row;
                if (m >= M) { sz = 0; m = 0; }
                g = (sel ? Al : Ah) + (size_t)m * K + k0 + qq * 8;
            } else {
                g = (sel == 2 ? Bh : Bl) + (size_t)row * K + k0 + qq * 8;
            }
            cp_async16(bo + seloff[sel] + row * 80 + qq * 16, g, sz);
        }
    };

    int nk = K / BK;
    issue_tile(0, 0);
    CP_COMMIT();
    if (nk > 1) { issue_tile(BK, 1); CP_COMMIT(); }

    int arow = lane & 15, ak = (lane >> 4) * 8;
    int brow = (lane & 7) + ((lane >> 4) << 3), bk = ((lane >> 3) & 1) * 8;

    for (int i = 0; i < nk; i++) {
        if (i + 2 < nk) CP_WAIT1(); else CP_WAIT0();
        __syncthreads();
        if (i + 2 < nk) {
            issue_tile((i + 2) * BK, (i + 2) % NSTAGE);
            CP_COMMIT();
        }
        const char* sb = sm + (i % NSTAGE) * STG;
        const __nv_bfloat16* sAh = (const __nv_bfloat16*)(sb + OFF_AH);
        const __nv_bfloat16* sAl = (const __nv_bfloat16*)(sb + OFF_AL);
        const __nv_bfloat16* sBh = (const __nv_bfloat16*)(sb + OFF_BH);
        const __nv_bfloat16* sBl = (const __nv_bfloat16*)(sb + OFF_BL);

#pragma unroll
        for (int kf = 0; kf < 2; kf++) {
            int c0 = kf * 16;
            uint32_t ah[2][4], al[2][4], bhf[4][2], blf[4][2];
#pragma unroll
            for (int mf = 0; mf < 2; mf++) {
                int r = (wm * 32 + mf * 16 + arow) * AST + c0 + ak;
                ldsm4(ah[mf], &sAh[r]);
                ldsm4(al[mf], &sAl[r]);
            }
#pragma unroll
            for (int nfp = 0; nfp < 2; nfp++) {
                int r = (wn * 32 + nfp * 16 + brow) * AST + c0 + bk;
                uint32_t tb[4], tl[4];
                ldsm4(tb, &sBh[r]);
                ldsm4(tl, &sBl[r]);
                bhf[2 * nfp][0] = tb[0]; bhf[2 * nfp][1] = tb[1];
                bhf[2 * nfp + 1][0] = tb[2]; bhf[2 * nfp + 1][1] = tb[3];
                blf[2 * nfp][0] = tl[0]; blf[2 * nfp][1] = tl[1];
                blf[2 * nfp + 1][0] = tl[2]; blf[2 * nfp + 1][1] = tl[3];
            }
#pragma unroll
            for (int mf = 0; mf < 2; mf++)
#pragma unroll
                for (int nf = 0; nf < 4; nf++) {
                    mma16816(acc[mf][nf], ah[mf], bhf[nf]);
                    mma16816(acc[mf][nf], ah[mf], blf[nf]);
                    mma16816(acc[mf][nf], al[mf], bhf[nf]);
                }
        }
    }

    // ---- epilogue: store C, fused score dot products ----
    float sp[2][2][2];
#pragma unroll
    for (int mf = 0; mf < 2; mf++)
#pragma unroll
        for (int h = 0; h < 2; h++) { sp[mf][h][0] = 0.f; sp[mf][h][1] = 0.f; }

#pragma unroll
    for (int mf = 0; mf < 2; mf++) {
        int r = wm * 32 + mf * 16 + q;
        int mr = m0 + r;
#pragma unroll
        for (int nf = 0; nf < 4; nf++) {
            int c = wn * 32 + nf * 8 + cq;
            float d0 = acc[mf][nf][0], d1 = acc[mf][nf][1];
            float d2 = acc[mf][nf][2], d3 = acc[mf][nf][3];
            if (mr < M) *(float2*)&C[(size_t)mr * ldc + coloff + c] = make_float2(d0, d1);
            if (mr + 8 < M) *(float2*)&C[(size_t)(mr + 8) * ldc + coloff + c] = make_float2(d2, d3);
            float a0 = att[c], a1 = att[c + 1], a2 = att[FH + c], a3 = att[FH + c + 1];
            sp[mf][0][0] = fmaf(d0, a0, fmaf(d1, a1, sp[mf][0][0]));
            sp[mf][0][1] = fmaf(d0, a2, fmaf(d1, a3, sp[mf][0][1]));
            sp[mf][1][0] = fmaf(d2, a0, fmaf(d3, a1, sp[mf][1][0]));
            sp[mf][1][1] = fmaf(d2, a2, fmaf(d3, a3, sp[mf][1][1]));
        }
    }
#pragma unroll
    for (int mf = 0; mf < 2; mf++)
#pragma unroll
        for (int h = 0; h < 2; h++)
#pragma unroll
            for (int sc = 0; sc < 2; sc++) {
                float v = sp[mf][h][sc];
                v += __shfl_xor_sync(0xffffffffu, v, 1);
                v += __shfl_xor_sync(0xffffffffu, v, 2);
                sp[mf][h][sc] = v;
            }
    if ((lane & 3) == 0) {
#pragma unroll
        for (int mf = 0; mf < 2; mf++)
#pragma unroll
            for (int h = 0; h < 2; h++) {
                int r = wm * 32 + mf * 16 + q + h * 8;
                redp[(wn * BM + r) * 2 + 0] = sp[mf][h][0];
                redp[(wn * BM + r) * 2 + 1] = sp[mf][h][1];
            }
    }
    __syncthreads();
    if (tid < BM) {
        int m = m0 + tid;
        if (m < M) {
            Ss[(size_t)m * sstride + bidy] = redp[tid * 2] + redp[(BM + tid) * 2];
            Sd[(size_t)m * sstride + bidy] = redp[tid * 2 + 1] + redp[(BM + tid) * 2 + 1];
        }
    }
}

// ---------------- layer-1 aggregation (8 heads fused, unroll x4) -----------
__global__ __launch_bounds__(128) void k_agg1() {
    int n = blockIdx.x, t = threadIdx.x;
    int head = t >> 4;
    float ss = g_S1s[n * NHEADS + head];
    float4 a0 = make_float4(0.f, 0.f, 0.f, 0.f);
    float4 a1 = make_float4(0.f, 0.f, 0.f, 0.f);
    float4 a2 = make_float4(0.f, 0.f, 0.f, 0.f);
    float4 a3 = make_float4(0.f, 0.f, 0.f, 0.f);
    float r0 = 0.f, r1 = 0.f, r2 = 0.f, r3 = 0.f;
    int beg = g_rowptr[n], end = g_rowptr[n + 1];
    int e = beg;
    for (; e + 3 < end; e += 4) {
        int d0 = g_dsts[e], d1 = g_dsts[e + 1], d2 = g_dsts[e + 2], d3 = g_dsts[e + 3];
        float s0 = g_S1d[d0 * NHEADS + head];
        float s1 = g_S1d[d1 * NHEADS + head];
        float s2 = g_S1d[d2 * NHEADS + head];
        float s3 = g_S1d[d3 * NHEADS + head];
        float4 h0 = *(const float4*)&g_H1[(size_t)d0 * D1 + t * 4];
        float4 h1 = *(const float4*)&g_H1[(size_t)d1 * D1 + t * 4];
        float4 h2 = *(const float4*)&g_H1[(size_t)d2 * D1 + t * 4];
        float4 h3 = *(const float4*)&g_H1[(size_t)d3 * D1 + t * 4];
        float w0 = __expf(-leakyv(ss + s0));
        float w1 = __expf(-leakyv(ss + s1));
        float w2 = __expf(-leakyv(ss + s2));
        float w3 = __expf(-leakyv(ss + s3));
        a0.x = fmaf(w0, h0.x, a0.x); a0.y = fmaf(w0, h0.y, a0.y);
        a0.z = fmaf(w0, h0.z, a0.z); a0.w = fmaf(w0, h0.w, a0.w);
        a1.x = fmaf(w1, h1.x, a1.x); a1.y = fmaf(w1, h1.y, a1.y);
        a1.z = fmaf(w1, h1.z, a1.z); a1.w = fmaf(w1, h1.w, a1.w);
        a2.x = fmaf(w2, h2.x, a2.x); a2.y = fmaf(w2, h2.y, a2.y);
        a2.z = fmaf(w2, h2.z, a2.z); a2.w = fmaf(w2, h2.w, a2.w);
        a3.x = fmaf(w3, h3.x, a3.x); a3.y = fmaf(w3, h3.y, a3.y);
        a3.z = fmaf(w3, h3.z, a3.z); a3.w = fmaf(w3, h3.w, a3.w);
        r0 += w0; r1 += w1; r2 += w2; r3 += w3;
    }
    for (; e < end; e++) {
        int d0 = g_dsts[e];
        float s0 = g_S1d[d0 * NHEADS + head];
        float4 h0 = *(const float4*)&g_H1[(size_t)d0 * D1 + t * 4];
        float w0 = __expf(-leakyv(ss + s0));
        a0.x = fmaf(w0, h0.x, a0.x); a0.y = fmaf(w0, h0.y, a0.y);
        a0.z = fmaf(w0, h0.z, a0.z); a0.w = fmaf(w0, h0.w, a0.w);
        r0 += w0;
    }
    float inv = 1.f / ((r0 + r1) + (r2 + r3));
    float o[4] = { eluv((a0.x + a1.x + a2.x + a3.x) * inv),
                   eluv((a0.y + a1.y + a2.y + a3.y) * inv),
                   eluv((a0.z + a1.z + a2.z + a3.z) * inv),
                   eluv((a0.w + a1.w + a2.w + a3.w) * inv) };
    size_t base = (size_t)n * D1 + t * 4;
    __nv_bfloat16 hh[4], ll[4];
#pragma unroll
    for (int j = 0; j < 4; j++) {
        hh[j] = __float2bfloat16(o[j]);
        ll[j] = __float2bfloat16(o[j] - __bfloat162float(hh[j]));
    }
    __nv_bfloat162* ph = (__nv_bfloat162*)&g_xch[base];
    __nv_bfloat162* pl = (__nv_bfloat162*)&g_xcl[base];
    ph[0] = __halves2bfloat162(hh[0], hh[1]); ph[1] = __halves2bfloat162(hh[2], hh[3]);
    pl[0] = __halves2bfloat162(ll[0], ll[1]); pl[1] = __halves2bfloat162(ll[2], ll[3]);
}

// ---------------- layer-2 aggregation + fused classifier -------------------
// 2 nodes per 128-thread block; XO kept in smem, 40-class dots fused.
__global__ __launch_bounds__(128) void k_agg2f(const float* __restrict__ mw,
                                               const float* __restrict__ mb,
                                               float* __restrict__ out) {
    __shared__ float xos[2][FH];
    int sub = threadIdx.x >> 6, t = threadIdx.x & 63;
    int n = blockIdx.x * 2 + sub;
    float ss = g_S2s[n];
    float acc0 = 0.f, acc1 = 0.f, rs0 = 0.f, rs1 = 0.f;
    int beg = g_rowptr[n], end = g_rowptr[n + 1];
    int e = beg;
    for (; e + 1 < end; e += 2) {
        int d0 = g_dsts[e], d1 = g_dsts[e + 1];
        float sd0 = g_S2d[d0], sd1 = g_S2d[d1];
        float v0 = g_H2[(size_t)d0 * FH + t];
        float v1 = g_H2[(size_t)d1 * FH + t];
        float w0 = __expf(-leakyv(ss + sd0));
        float w1 = __expf(-leakyv(ss + sd1));
        acc0 = fmaf(w0, v0, acc0); rs0 += w0;
        acc1 = fmaf(w1, v1, acc1); rs1 += w1;
    }
    if (e < end) {
        int d0 = g_dsts[e];
        float w0 = __expf(-leakyv(ss + g_S2d[d0]));
        acc0 = fmaf(w0, g_H2[(size_t)d0 * FH + t], acc0); rs0 += w0;
    }
    xos[sub][t] = eluv((acc0 + acc1) / (rs0 + rs1));
    __syncthreads();
    if (threadIdx.x < 2 * NCLASSF) {
        int s2 = threadIdx.x / NCLASSF, c = threadIdx.x % NCLASSF;
        int n2 = blockIdx.x * 2 + s2;
        const float4* wv = (const float4*)&mw[c * FH];
        const float4* xo = (const float4*)xos[s2];
        float s = mb[c];
#pragma unroll
        for (int k = 0; k < FH / 4; k++) {
            float4 a = xo[k], b = wv[k];
            s = fmaf(a.x, b.x, s); s = fmaf(a.y, b.y, s);
            s = fmaf(a.z, b.z, s); s = fmaf(a.w, b.w, s);
        }
        out[(size_t)n2 * NCLASSF + c] = s;
    }
}

// ---------------- launch (fork-join multi-stream capture) -------------------
extern "C" void kernel_launch(void* const* d_in, const int* in_sizes, int n_in,
                              void* d_out, int out_size) {
    const float* x  = (const float*)d_in[0];
    const int*   ei = (const int*)d_in[1];
    const float* W  = (const float*)d_in[2];
    const float* a  = (const float*)d_in[3];
    const float* Wo = (const float*)d_in[4];
    const float* ao = (const float*)d_in[5];
    const float* mw = (const float*)d_in[6];
    const float* mb = (const float*)d_in[7];
    float* out = (float*)d_out;

    const int* src = ei;
    const int* dst = ei + N_EDGES;

    float *pH1, *pH2, *pS1s, *pS1d, *pS2s, *pS2d;
    __nv_bfloat16 *pxh, *pxl, *pwth, *pwtl, *pwoth, *pwotl, *pxch, *pxcl;
    cudaGetSymbolAddress((void**)&pH1, g_H1);
    cudaGetSymbolAddress((void**)&pH2, g_H2);
    cudaGetSymbolAddress((void**)&pS1s, g_S1s);
    cudaGetSymbolAddress((void**)&pS1d, g_S1d);
    cudaGetSymbolAddress((void**)&pS2s, g_S2s);
    cudaGetSymbolAddress((void**)&pS2d, g_S2d);
    cudaGetSymbolAddress((void**)&pxh, g_xh);
    cudaGetSymbolAddress((void**)&pxl, g_xl);
    cudaGetSymbolAddress((void**)&pwth, g_wth);
    cudaGetSymbolAddress((void**)&pwtl, g_wtl);
    cudaGetSymbolAddress((void**)&pwoth, g_woth);
    cudaGetSymbolAddress((void**)&pwotl, g_wotl);
    cudaGetSymbolAddress((void**)&pxch, g_xch);
    cudaGetSymbolAddress((void**)&pxcl, g_xcl);

    cudaFuncSetAttribute(k_gemm_mma, cudaFuncAttributeMaxDynamicSharedMemorySize, GSMEM);

    cudaStream_t s2;
    cudaStreamCreate(&s2);
    cudaEvent_t evF, evJ;
    cudaEventCreateWithFlags(&evF, cudaEventDisableTiming);
    cudaEventCreateWithFlags(&evJ, cudaEventDisableTiming);

    // fork: side stream runs the CSR chain + Wo split
    cudaEventRecord(evF, 0);
    cudaStreamWaitEvent(s2, evF, 0);
    k_zero_cnt<<<(N_NODES + 255) / 256, 256, 0, s2>>>();
    k_hist<<<(N_EDGES + 255) / 256, 256, 0, s2>>>(src);
    k_scan<<<1, 1024, 0, s2>>>();
    k_scatter<<<(N_EDGES + 255) / 256, 256, 0, s2>>>(src, dst);
    k_split_wot<<<(D1 * FH + 255) / 256, 256, 0, s2>>>(Wo, pwoth, pwotl);
    cudaEventRecord(evJ, s2);

    // main stream: splits + GEMM1 (overlaps CSR chain)
    k_split_x<<<(N_NODES * F_INF / 4 + 255) / 256, 256>>>(x, pxh, pxl, N_NODES * F_INF / 4);
    k_split_wt<<<(NHEADS * F_INF * FH + 255) / 256, 256>>>(W, pwth, pwtl);
    dim3 g1((N_NODES + BM - 1) / BM, NHEADS);
    k_gemm_mma<<<g1, 256, GSMEM>>>(pxh, pxl, pwth, pwtl, N_NODES, F_INF,
                                   pH1, D1, a, pS1s, pS1d, NHEADS);

    // join: aggregation needs CSR + GEMM1
    cudaStreamWaitEvent(0, evJ, 0);
    k_agg1<<<N_NODES, 128>>>();

    dim3 g2((N_NODES + BM - 1) / BM, 1);
    k_gemm_mma<<<g2, 256, GSMEM>>>(pxch, pxcl, pwoth, pwotl, N_NODES, D1,
                                   pH2, FH, ao, pS2s, pS2d, 1);
    k_agg2f<<<N_NODES / 2, 128>>>(mw, mb, out);

    cudaEventDestroy(evF);
    cudaEventDestroy(evJ);
    cudaStreamDestroy(s2);
}

// round 9
// speedup vs baseline: 2.4270x; 1.0446x over previous
#include <cuda_runtime.h>
#include <cuda_bf16.h>
#include <cuda_fp16.h>
#include <cstdint>

#define N_NODES 50000
#define N_EDGES 850000
#define F_INF   256
#define FH      64
#define NHEADS  8
#define NCLASSF 40
#define ALPHAF  0.2f
#define D1      (NHEADS * FH)   // 512

// ---------------- device scratch ----------------
__device__ __half g_H1h[(size_t)N_NODES * D1];   // layer-1 features (fp16)
__device__ float g_S1s[N_NODES * NHEADS];
__device__ float g_S1d[N_NODES * NHEADS];
__device__ float g_H2[(size_t)N_NODES * FH];
__device__ float g_S2s[N_NODES];
__device__ float g_S2d[N_NODES];
__device__ int   g_rowptr[N_NODES + 1];
__device__ int   g_cnt[N_NODES];
__device__ int   g_pos[N_NODES];
__device__ int   g_dsts[N_EDGES];
// bf16 split operands
__device__ __nv_bfloat16 g_xh[(size_t)N_NODES * F_INF];
__device__ __nv_bfloat16 g_xl[(size_t)N_NODES * F_INF];
__device__ __nv_bfloat16 g_wth[NHEADS * FH * F_INF];
__device__ __nv_bfloat16 g_wtl[NHEADS * FH * F_INF];
__device__ __nv_bfloat16 g_woth[FH * D1];
__device__ __nv_bfloat16 g_wotl[FH * D1];
__device__ __nv_bfloat16 g_xch[(size_t)N_NODES * D1];
__device__ __nv_bfloat16 g_xcl[(size_t)N_NODES * D1];

__device__ __forceinline__ float leakyv(float v) { return v > 0.f ? v : ALPHAF * v; }
__device__ __forceinline__ float eluv(float v)   { return v > 0.f ? v : expm1f(v); }
__device__ __forceinline__ float4 ldh4(const __half* p) {
    uint2 u = *(const uint2*)p;
    __half2 h0 = *reinterpret_cast<__half2*>(&u.x);
    __half2 h1 = *reinterpret_cast<__half2*>(&u.y);
    float2 f0 = __half22float2(h0), f1 = __half22float2(h1);
    return make_float4(f0.x, f0.y, f1.x, f1.y);
}

// ---------------- CSR build ----------------
__global__ void k_zero_cnt() {
    int i = blockIdx.x * blockDim.x + threadIdx.x;
    if (i < N_NODES) g_cnt[i] = 0;
}
__global__ void k_hist(const int* __restrict__ src) {
    int e = blockIdx.x * blockDim.x + threadIdx.x;
    if (e < N_EDGES) atomicAdd(&g_cnt[src[e]], 1);
}
__global__ __launch_bounds__(1024) void k_scan() {
    __shared__ int s[1024];
    const int CH = 49;
    int t = threadIdx.x;
    int start = t * CH;
    int end = start + CH; if (end > N_NODES) end = N_NODES;
    int sum = 0;
    for (int i = start; i < end; i++) sum += g_cnt[i];
    s[t] = sum;
    __syncthreads();
    for (int off = 1; off < 1024; off <<= 1) {
        int v = (t >= off) ? s[t - off] : 0;
        __syncthreads();
        s[t] += v;
        __syncthreads();
    }
    int run = (t == 0) ? 0 : s[t - 1];
    for (int i = start; i < end; i++) {
        g_rowptr[i] = run;
        g_pos[i] = run;
        run += g_cnt[i];
    }
    if (t == 0) g_rowptr[N_NODES] = s[1023];
}
__global__ void k_scatter(const int* __restrict__ src, const int* __restrict__ dst) {
    int e = blockIdx.x * blockDim.x + threadIdx.x;
    if (e < N_EDGES) {
        int p = atomicAdd(&g_pos[src[e]], 1);
        g_dsts[p] = dst[e];
    }
}

// ---------------- bf16 hi/lo splits ----------------
__global__ void k_split_x(const float* __restrict__ x, __nv_bfloat16* __restrict__ oh,
                          __nv_bfloat16* __restrict__ ol, int n4) {
    int i = blockIdx.x * blockDim.x + threadIdx.x;
    if (i >= n4) return;
    float4 v = ((const float4*)x)[i];
    __nv_bfloat16 h0 = __float2bfloat16(v.x), h1 = __float2bfloat16(v.y);
    __nv_bfloat16 h2 = __float2bfloat16(v.z), h3 = __float2bfloat16(v.w);
    __nv_bfloat16 l0 = __float2bfloat16(v.x - __bfloat162float(h0));
    __nv_bfloat16 l1 = __float2bfloat16(v.y - __bfloat162float(h1));
    __nv_bfloat16 l2 = __float2bfloat16(v.z - __bfloat162float(h2));
    __nv_bfloat16 l3 = __float2bfloat16(v.w - __bfloat162float(h3));
    __nv_bfloat162* ph = (__nv_bfloat162*)(oh) + i * 2;
    __nv_bfloat162* pl = (__nv_bfloat162*)(ol) + i * 2;
    ph[0] = __halves2bfloat162(h0, h1); ph[1] = __halves2bfloat162(h2, h3);
    pl[0] = __halves2bfloat162(l0, l1); pl[1] = __halves2bfloat162(l2, l3);
}
// W[h][k][n] (fp32) -> out[h][n][k] bf16 hi/lo
__global__ void k_split_wt(const float* __restrict__ W, __nv_bfloat16* __restrict__ oh,
                           __nv_bfloat16* __restrict__ ol) {
    int i = blockIdx.x * blockDim.x + threadIdx.x;
    if (i >= NHEADS * F_INF * FH) return;
    int h = i / (F_INF * FH), r = i % (F_INF * FH), k = r / FH, n = r % FH;
    float v = W[i];
    __nv_bfloat16 hh = __float2bfloat16(v);
    __nv_bfloat16 ll = __float2bfloat16(v - __bfloat162float(hh));
    size_t o = (size_t)(h * FH + n) * F_INF + k;
    oh[o] = hh; ol[o] = ll;
}
// Wo[k][n] -> out[n][k]
__global__ void k_split_wot(const float* __restrict__ Wo, __nv_bfloat16* __restrict__ oh,
                            __nv_bfloat16* __restrict__ ol) {
    int i = blockIdx.x * blockDim.x + threadIdx.x;
    if (i >= D1 * FH) return;
    int k = i / FH, n = i % FH;
    float v = Wo[i];
    __nv_bfloat16 hh = __float2bfloat16(v);
    __nv_bfloat16 ll = __float2bfloat16(v - __bfloat162float(hh));
    size_t o = (size_t)n * D1 + k;
    oh[o] = hh; ol[o] = ll;
}

// ---------------- mma.sync bf16x3 GEMM, 3-stage cp.async pipeline ----------
#define BM 128
#define BN 64
#define BK 32
#define AST 40                      // padded row stride in bf16 (80B)
#define STG 30720                   // bytes per pipeline stage
#define NSTAGE 3
#define OFF_AH 0
#define OFF_AL 10240
#define OFF_BH 20480
#define OFF_BL 25600
#define GSMEM  (NSTAGE * STG + 2048)

__device__ __forceinline__ void mma16816(float* d, const uint32_t* a, const uint32_t* b) {
    asm volatile(
        "mma.sync.aligned.m16n8k16.row.col.f32.bf16.bf16.f32 "
        "{%0,%1,%2,%3},{%4,%5,%6,%7},{%8,%9},{%0,%1,%2,%3};"
        : "+f"(d[0]), "+f"(d[1]), "+f"(d[2]), "+f"(d[3])
        : "r"(a[0]), "r"(a[1]), "r"(a[2]), "r"(a[3]), "r"(b[0]), "r"(b[1]));
}
__device__ __forceinline__ void ldsm4(uint32_t* r, const void* p) {
    uint32_t addr = (uint32_t)__cvta_generic_to_shared(p);
    asm volatile("ldmatrix.sync.aligned.m8n8.x4.shared.b16 {%0,%1,%2,%3}, [%4];"
                 : "=r"(r[0]), "=r"(r[1]), "=r"(r[2]), "=r"(r[3]) : "r"(addr));
}
__device__ __forceinline__ void cp_async16(uint32_t saddr, const void* g, int sz) {
    asm volatile("cp.async.cg.shared.global [%0], [%1], 16, %2;"
                 :: "r"(saddr), "l"(g), "r"(sz));
}
#define CP_COMMIT() asm volatile("cp.async.commit_group;")
#define CP_WAIT0()  asm volatile("cp.async.wait_group 0;")
#define CP_WAIT1()  asm volatile("cp.async.wait_group 1;")

// If Ch != nullptr, C is stored packed fp16 (layer-1 H1); else fp32 (layer-2 H2).
__global__ __launch_bounds__(256) void k_gemm_mma(
    const __nv_bfloat16* __restrict__ Ah, const __nv_bfloat16* __restrict__ Al,
    const __nv_bfloat16* __restrict__ Bh, const __nv_bfloat16* __restrict__ Bl,
    int M, int K, float* __restrict__ C, __half* __restrict__ Ch, int ldc,
    const float* __restrict__ att, float* __restrict__ Ss, float* __restrict__ Sd,
    int sstride)
{
    extern __shared__ char sm[];
    uint32_t sbase = (uint32_t)__cvta_generic_to_shared(sm);
    float* redp = (float*)(sm + NSTAGE * STG);   // [2][BM][2]

    int tid = threadIdx.x, lane = tid & 31, wid = tid >> 5;
    int wm = wid & 3, wn = wid >> 2;        // warp grid 4(m) x 2(n)
    int m0 = blockIdx.x * BM;
    int bidy = blockIdx.y;
    Bh += (size_t)bidy * FH * K;
    Bl += (size_t)bidy * FH * K;
    att += bidy * 2 * FH;
    int coloff = bidy * FH;

    float acc[2][4][4];
#pragma unroll
    for (int i = 0; i < 2; i++)
#pragma unroll
        for (int j = 0; j < 4; j++)
#pragma unroll
            for (int l = 0; l < 4; l++) acc[i][j][l] = 0.f;

    int q = lane >> 2, cq = (lane & 3) * 2;

    // per-thread staging map: 6 chunks of 16B; sel: 0 Ah,1 Al,2 Bh,3 Bl
    int st_row[6], st_q[6], st_sel[6];
#pragma unroll
    for (int l = 0; l < 6; l++) {
        int it = tid + l * 256;
        if (it < 1024) {
            int p = it >> 9, i = it & 511;
            st_sel[l] = p; st_row[l] = i >> 2; st_q[l] = i & 3;
        } else {
            int j = it - 1024, p = j >> 8, i = j & 255;
            st_sel[l] = 2 + p; st_row[l] = i >> 2; st_q[l] = i & 3;
        }
    }
    const int seloff[4] = {OFF_AH, OFF_AL, OFF_BH, OFF_BL};

    auto issue_tile = [&](int k0, int slot) {
        uint32_t bo = sbase + slot * STG;
#pragma unroll
        for (int l = 0; l < 6; l++) {
            int row = st_row[l], qq = st_q[l], sel = st_sel[l];
            const __nv_bfloat16* g;
            int sz = 16;
            if (sel < 2) {
                int m = m0 + row;
                if (m >= M) { sz = 0; m = 0; }
                g = (sel ? Al : Ah) + (size_t)m * K + k0 + qq * 8;
            } else {
                g = (sel == 2 ? Bh : Bl) + (size_t)row * K + k0 + qq * 8;
            }
            cp_async16(bo + seloff[sel] + row * 80 + qq * 16, g, sz);
        }
    };

    int nk = K / BK;
    issue_tile(0, 0);
    CP_COMMIT();
    if (nk > 1) { issue_tile(BK, 1); CP_COMMIT(); }

    int arow = lane & 15, ak = (lane >> 4) * 8;
    int brow = (lane & 7) + ((lane >> 4) << 3), bk = ((lane >> 3) & 1) * 8;

    for (int i = 0; i < nk; i++) {
        if (i + 2 < nk) CP_WAIT1(); else CP_WAIT0();
        __syncthreads();
        if (i + 2 < nk) {
            issue_tile((i + 2) * BK, (i + 2) % NSTAGE);
            CP_COMMIT();
        }
        const char* sb = sm + (i % NSTAGE) * STG;
        const __nv_bfloat16* sAh = (const __nv_bfloat16*)(sb + OFF_AH);
        const __nv_bfloat16* sAl = (const __nv_bfloat16*)(sb + OFF_AL);
        const __nv_bfloat16* sBh = (const __nv_bfloat16*)(sb + OFF_BH);
        const __nv_bfloat16* sBl = (const __nv_bfloat16*)(sb + OFF_BL);

#pragma unroll
        for (int kf = 0; kf < 2; kf++) {
            int c0 = kf * 16;
            uint32_t ah[2][4], al[2][4], bhf[4][2], blf[4][2];
#pragma unroll
            for (int mf = 0; mf < 2; mf++) {
                int r = (wm * 32 + mf * 16 + arow) * AST + c0 + ak;
                ldsm4(ah[mf], &sAh[r]);
                ldsm4(al[mf], &sAl[r]);
            }
#pragma unroll
            for (int nfp = 0; nfp < 2; nfp++) {
                int r = (wn * 32 + nfp * 16 + brow) * AST + c0 + bk;
                uint32_t tb[4], tl[4];
                ldsm4(tb, &sBh[r]);
                ldsm4(tl, &sBl[r]);
                bhf[2 * nfp][0] = tb[0]; bhf[2 * nfp][1] = tb[1];
                bhf[2 * nfp + 1][0] = tb[2]; bhf[2 * nfp + 1][1] = tb[3];
                blf[2 * nfp][0] = tl[0]; blf[2 * nfp][1] = tl[1];
                blf[2 * nfp + 1][0] = tl[2]; blf[2 * nfp + 1][1] = tl[3];
            }
#pragma unroll
            for (int mf = 0; mf < 2; mf++)
#pragma unroll
                for (int nf = 0; nf < 4; nf++) {
                    mma16816(acc[mf][nf], ah[mf], bhf[nf]);
                    mma16816(acc[mf][nf], ah[mf], blf[nf]);
                    mma16816(acc[mf][nf], al[mf], bhf[nf]);
                }
        }
    }

    // ---- epilogue: store C (fp32 or packed fp16), fused score dot products ----
    float sp[2][2][2];
#pragma unroll
    for (int mf = 0; mf < 2; mf++)
#pragma unroll
        for (int h = 0; h < 2; h++) { sp[mf][h][0] = 0.f; sp[mf][h][1] = 0.f; }

#pragma unroll
    for (int mf = 0; mf < 2; mf++) {
        int r = wm * 32 + mf * 16 + q;
        int mr = m0 + r;
#pragma unroll
        for (int nf = 0; nf < 4; nf++) {
            int c = wn * 32 + nf * 8 + cq;
            float d0 = acc[mf][nf][0], d1 = acc[mf][nf][1];
            float d2 = acc[mf][nf][2], d3 = acc[mf][nf][3];
            if (Ch) {
                if (mr < M)
                    *(__half2*)&Ch[(size_t)mr * ldc + coloff + c] = __floats2half2_rn(d0, d1);
                if (mr + 8 < M)
                    *(__half2*)&Ch[(size_t)(mr + 8) * ldc + coloff + c] = __floats2half2_rn(d2, d3);
            } else {
                if (mr < M) *(float2*)&C[(size_t)mr * ldc + coloff + c] = make_float2(d0, d1);
                if (mr + 8 < M) *(float2*)&C[(size_t)(mr + 8) * ldc + coloff + c] = make_float2(d2, d3);
            }
            float a0 = att[c], a1 = att[c + 1], a2 = att[FH + c], a3 = att[FH + c + 1];
            sp[mf][0][0] = fmaf(d0, a0, fmaf(d1, a1, sp[mf][0][0]));
            sp[mf][0][1] = fmaf(d0, a2, fmaf(d1, a3, sp[mf][0][1]));
            sp[mf][1][0] = fmaf(d2, a0, fmaf(d3, a1, sp[mf][1][0]));
            sp[mf][1][1] = fmaf(d2, a2, fmaf(d3, a3, sp[mf][1][1]));
        }
    }
#pragma unroll
    for (int mf = 0; mf < 2; mf++)
#pragma unroll
        for (int h = 0; h < 2; h++)
#pragma unroll
            for (int sc = 0; sc < 2; sc++) {
                float v = sp[mf][h][sc];
                v += __shfl_xor_sync(0xffffffffu, v, 1);
                v += __shfl_xor_sync(0xffffffffu, v, 2);
                sp[mf][h][sc] = v;
            }
    if ((lane & 3) == 0) {
#pragma unroll
        for (int mf = 0; mf < 2; mf++)
#pragma unroll
            for (int h = 0; h < 2; h++) {
                int r = wm * 32 + mf * 16 + q + h * 8;
                redp[(wn * BM + r) * 2 + 0] = sp[mf][h][0];
                redp[(wn * BM + r) * 2 + 1] = sp[mf][h][1];
            }
    }
    __syncthreads();
    if (tid < BM) {
        int m = m0 + tid;
        if (m < M) {
            Ss[(size_t)m * sstride + bidy] = redp[tid * 2] + redp[(BM + tid) * 2];
            Sd[(size_t)m * sstride + bidy] = redp[tid * 2 + 1] + redp[(BM + tid) * 2 + 1];
        }
    }
}

// ---------------- layer-1 aggregation (8 heads fused, fp16 gather) ---------
__global__ __launch_bounds__(128) void k_agg1() {
    int n = blockIdx.x, t = threadIdx.x;
    int head = t >> 4;
    float ss = g_S1s[n * NHEADS + head];
    float4 a0 = make_float4(0.f, 0.f, 0.f, 0.f);
    float4 a1 = make_float4(0.f, 0.f, 0.f, 0.f);
    float4 a2 = make_float4(0.f, 0.f, 0.f, 0.f);
    float4 a3 = make_float4(0.f, 0.f, 0.f, 0.f);
    float r0 = 0.f, r1 = 0.f, r2 = 0.f, r3 = 0.f;
    int beg = g_rowptr[n], end = g_rowptr[n + 1];
    int e = beg;
    for (; e + 3 < end; e += 4) {
        int d0 = g_dsts[e], d1 = g_dsts[e + 1], d2 = g_dsts[e + 2], d3 = g_dsts[e + 3];
        float s0 = g_S1d[d0 * NHEADS + head];
        float s1 = g_S1d[d1 * NHEADS + head];
        float s2 = g_S1d[d2 * NHEADS + head];
        float s3 = g_S1d[d3 * NHEADS + head];
        float4 h0 = ldh4(&g_H1h[(size_t)d0 * D1 + t * 4]);
        float4 h1 = ldh4(&g_H1h[(size_t)d1 * D1 + t * 4]);
        float4 h2 = ldh4(&g_H1h[(size_t)d2 * D1 + t * 4]);
        float4 h3 = ldh4(&g_H1h[(size_t)d3 * D1 + t * 4]);
        float w0 = __expf(-leakyv(ss + s0));
        float w1 = __expf(-leakyv(ss + s1));
        float w2 = __expf(-leakyv(ss + s2));
        float w3 = __expf(-leakyv(ss + s3));
        a0.x = fmaf(w0, h0.x, a0.x); a0.y = fmaf(w0, h0.y, a0.y);
        a0.z = fmaf(w0, h0.z, a0.z); a0.w = fmaf(w0, h0.w, a0.w);
        a1.x = fmaf(w1, h1.x, a1.x); a1.y = fmaf(w1, h1.y, a1.y);
        a1.z = fmaf(w1, h1.z, a1.z); a1.w = fmaf(w1, h1.w, a1.w);
        a2.x = fmaf(w2, h2.x, a2.x); a2.y = fmaf(w2, h2.y, a2.y);
        a2.z = fmaf(w2, h2.z, a2.z); a2.w = fmaf(w2, h2.w, a2.w);
        a3.x = fmaf(w3, h3.x, a3.x); a3.y = fmaf(w3, h3.y, a3.y);
        a3.z = fmaf(w3, h3.z, a3.z); a3.w = fmaf(w3, h3.w, a3.w);
        r0 += w0; r1 += w1; r2 += w2; r3 += w3;
    }
    for (; e < end; e++) {
        int d0 = g_dsts[e];
        float s0 = g_S1d[d0 * NHEADS + head];
        float4 h0 = ldh4(&g_H1h[(size_t)d0 * D1 + t * 4]);
        float w0 = __expf(-leakyv(ss + s0));
        a0.x = fmaf(w0, h0.x, a0.x); a0.y = fmaf(w0, h0.y, a0.y);
        a0.z = fmaf(w0, h0.z, a0.z); a0.w = fmaf(w0, h0.w, a0.w);
        r0 += w0;
    }
    float inv = 1.f / ((r0 + r1) + (r2 + r3));
    float o[4] = { eluv((a0.x + a1.x + a2.x + a3.x) * inv),
                   eluv((a0.y + a1.y + a2.y + a3.y) * inv),
                   eluv((a0.z + a1.z + a2.z + a3.z) * inv),
                   eluv((a0.w + a1.w + a2.w + a3.w) * inv) };
    size_t base = (size_t)n * D1 + t * 4;
    __nv_bfloat16 hh[4], ll[4];
#pragma unroll
    for (int j = 0; j < 4; j++) {
        hh[j] = __float2bfloat16(o[j]);
        ll[j] = __float2bfloat16(o[j] - __bfloat162float(hh[j]));
    }
    __nv_bfloat162* ph = (__nv_bfloat162*)&g_xch[base];
    __nv_bfloat162* pl = (__nv_bfloat162*)&g_xcl[base];
    ph[0] = __halves2bfloat162(hh[0], hh[1]); ph[1] = __halves2bfloat162(hh[2], hh[3]);
    pl[0] = __halves2bfloat162(ll[0], ll[1]); pl[1] = __halves2bfloat162(ll[2], ll[3]);
}

// ---------------- layer-2 aggregation + fused classifier -------------------
__global__ __launch_bounds__(128) void k_agg2f(const float* __restrict__ mw,
                                               const float* __restrict__ mb,
                                               float* __restrict__ out) {
    __shared__ float xos[2][FH];
    int sub = threadIdx.x >> 6, t = threadIdx.x & 63;
    int n = blockIdx.x * 2 + sub;
    float ss = g_S2s[n];
    float acc0 = 0.f, acc1 = 0.f, rs0 = 0.f, rs1 = 0.f;
    int beg = g_rowptr[n], end = g_rowptr[n + 1];
    int e = beg;
    for (; e + 1 < end; e += 2) {
        int d0 = g_dsts[e], d1 = g_dsts[e + 1];
        float sd0 = g_S2d[d0], sd1 = g_S2d[d1];
        float v0 = g_H2[(size_t)d0 * FH + t];
        float v1 = g_H2[(size_t)d1 * FH + t];
        float w0 = __expf(-leakyv(ss + sd0));
        float w1 = __expf(-leakyv(ss + sd1));
        acc0 = fmaf(w0, v0, acc0); rs0 += w0;
        acc1 = fmaf(w1, v1, acc1); rs1 += w1;
    }
    if (e < end) {
        int d0 = g_dsts[e];
        float w0 = __expf(-leakyv(ss + g_S2d[d0]));
        acc0 = fmaf(w0, g_H2[(size_t)d0 * FH + t], acc0); rs0 += w0;
    }
    xos[sub][t] = eluv((acc0 + acc1) / (rs0 + rs1));
    __syncthreads();
    if (threadIdx.x < 2 * NCLASSF) {
        int s2 = threadIdx.x / NCLASSF, c = threadIdx.x % NCLASSF;
        int n2 = blockIdx.x * 2 + s2;
        const float4* wv = (const float4*)&mw[c * FH];
        const float4* xo = (const float4*)xos[s2];
        float s = mb[c];
#pragma unroll
        for (int k = 0; k < FH / 4; k++) {
            float4 a = xo[k], b = wv[k];
            s = fmaf(a.x, b.x, s); s = fmaf(a.y, b.y, s);
            s = fmaf(a.z, b.z, s); s = fmaf(a.w, b.w, s);
        }
        out[(size_t)n2 * NCLASSF + c] = s;
    }
}

// ---------------- launch (fork-join multi-stream capture) -------------------
extern "C" void kernel_launch(void* const* d_in, const int* in_sizes, int n_in,
                              void* d_out, int out_size) {
    const float* x  = (const float*)d_in[0];
    const int*   ei = (const int*)d_in[1];
    const float* W  = (const float*)d_in[2];
    const float* a  = (const float*)d_in[3];
    const float* Wo = (const float*)d_in[4];
    const float* ao = (const float*)d_in[5];
    const float* mw = (const float*)d_in[6];
    const float* mb = (const float*)d_in[7];
    float* out = (float*)d_out;

    const int* src = ei;
    const int* dst = ei + N_EDGES;

    float *pH2, *pS1s, *pS1d, *pS2s, *pS2d;
    __half* pH1h;
    __nv_bfloat16 *pxh, *pxl, *pwth, *pwtl, *pwoth, *pwotl, *pxch, *pxcl;
    cudaGetSymbolAddress((void**)&pH1h, g_H1h);
    cudaGetSymbolAddress((void**)&pH2, g_H2);
    cudaGetSymbolAddress((void**)&pS1s, g_S1s);
    cudaGetSymbolAddress((void**)&pS1d, g_S1d);
    cudaGetSymbolAddress((void**)&pS2s, g_S2s);
    cudaGetSymbolAddress((void**)&pS2d, g_S2d);
    cudaGetSymbolAddress((void**)&pxh, g_xh);
    cudaGetSymbolAddress((void**)&pxl, g_xl);
    cudaGetSymbolAddress((void**)&pwth, g_wth);
    cudaGetSymbolAddress((void**)&pwtl, g_wtl);
    cudaGetSymbolAddress((void**)&pwoth, g_woth);
    cudaGetSymbolAddress((void**)&pwotl, g_wotl);
    cudaGetSymbolAddress((void**)&pxch, g_xch);
    cudaGetSymbolAddress((void**)&pxcl, g_xcl);

    cudaFuncSetAttribute(k_gemm_mma, cudaFuncAttributeMaxDynamicSharedMemorySize, GSMEM);

    cudaStream_t s2;
    cudaStreamCreate(&s2);
    cudaEvent_t evF, evJ;
    cudaEventCreateWithFlags(&evF, cudaEventDisableTiming);
    cudaEventCreateWithFlags(&evJ, cudaEventDisableTiming);

    // fork: side stream runs the CSR chain + Wo split
    cudaEventRecord(evF, 0);
    cudaStreamWaitEvent(s2, evF, 0);
    k_zero_cnt<<<(N_NODES + 255) / 256, 256, 0, s2>>>();
    k_hist<<<(N_EDGES + 255) / 256, 256, 0, s2>>>(src);
    k_scan<<<1, 1024, 0, s2>>>();
    k_scatter<<<(N_EDGES + 255) / 256, 256, 0, s2>>>(src, dst);
    k_split_wot<<<(D1 * FH + 255) / 256, 256, 0, s2>>>(Wo, pwoth, pwotl);
    cudaEventRecord(evJ, s2);

    // main stream: splits + GEMM1 (overlaps CSR chain)
    k_split_x<<<(N_NODES * F_INF / 4 + 255) / 256, 256>>>(x, pxh, pxl, N_NODES * F_INF / 4);
    k_split_wt<<<(NHEADS * F_INF * FH + 255) / 256, 256>>>(W, pwth, pwtl);
    dim3 g1((N_NODES + BM - 1) / BM, NHEADS);
    k_gemm_mma<<<g1, 256, GSMEM>>>(pxh, pxl, pwth, pwtl, N_NODES, F_INF,
                                   nullptr, pH1h, D1, a, pS1s, pS1d, NHEADS);

    // join: aggregation needs CSR + GEMM1
    cudaStreamWaitEvent(0, evJ, 0);
    k_agg1<<<N_NODES, 128>>>();

    dim3 g2((N_NODES + BM - 1) / BM, 1);
    k_gemm_mma<<<g2, 256, GSMEM>>>(pxch, pxcl, pwoth, pwotl, N_NODES, D1,
                                   pH2, nullptr, FH, ao, pS2s, pS2d, 1);
    k_agg2f<<<N_NODES / 2, 128>>>(mw, mb, out);

    cudaEventDestroy(evF);
    cudaEventDestroy(evJ);
    cudaStreamDestroy(s2);
}